// round 8
// baseline (speedup 1.0000x reference)
#include <cuda_runtime.h>
#include <cuda_bf16.h>
#include <math.h>
#include <stdint.h>

#define NA   8192
#define NE   262144
#define NMOL 128
#define FF   128
#define RR   20
#define LL   3
#define PI_F 3.14159265358979f

// ---------------- scratch (device globals; no runtime alloc allowed) -------
__device__ float g_s  [NA * FF];
__device__ float g_vA [NA * 3 * FF];
__device__ float g_vB [NA * 3 * FF];
__device__ float g_h  [NA * FF];
__device__ float g_phi[NA * 3 * FF];
__device__ float g_uvv[NA * 3 * 2 * FF];      // fused [atom*3][256]: uv | vv
__device__ float g_a  [NA * 3 * FF];
__device__ float g_egeo[NE * 24];             // per sorted edge: rbf*fc[20], fc, unit[3]
__device__ int   g_esrc[NE];
__device__ int   g_rowstart[NA + 1];
__device__ int   g_cursor[NA];
__device__ int   g_count[NA];
// bf16 hi/lo weight blobs, N-major [n][k]
#define WBLOB_ELEMS (34 * 16384)
__device__ __nv_bfloat16 g_whi[WBLOB_ELEMS];
__device__ __nv_bfloat16 g_wlo[WBLOB_ELEMS];
// bf16 hi/lo activation (A-operand) arrays, k-major rows
__device__ __nv_bfloat16 g_sh [NA * FF],     g_sl [NA * FF];
__device__ __nv_bfloat16 g_vbh[NA * 3 * FF], g_vbl[NA * 3 * FF];
__device__ __nv_bfloat16 g_cth[NA * 2 * FF], g_ctl[NA * 2 * FF];

// ---------------- packed f32x2 helpers --------------------------------------
__device__ __forceinline__ float2 ffma2(float2 a, float2 b, float2 c) {
    float2 d;
    asm("fma.rn.f32x2 %0, %1, %2, %3;"
        : "=l"(*reinterpret_cast<unsigned long long*>(&d))
        : "l"(*reinterpret_cast<unsigned long long*>(&a)),
          "l"(*reinterpret_cast<unsigned long long*>(&b)),
          "l"(*reinterpret_cast<unsigned long long*>(&c)));
    return d;
}
__device__ __forceinline__ float2 fmul2(float2 a, float2 b) {
    float2 d;
    asm("mul.rn.f32x2 %0, %1, %2;"
        : "=l"(*reinterpret_cast<unsigned long long*>(&d))
        : "l"(*reinterpret_cast<unsigned long long*>(&a)),
          "l"(*reinterpret_cast<unsigned long long*>(&b)));
    return d;
}
__device__ __forceinline__ float2 fadd2(float2 a, float2 b) {
    float2 d;
    asm("add.rn.f32x2 %0, %1, %2;"
        : "=l"(*reinterpret_cast<unsigned long long*>(&d))
        : "l"(*reinterpret_cast<unsigned long long*>(&a)),
          "l"(*reinterpret_cast<unsigned long long*>(&b)));
    return d;
}
__device__ __forceinline__ void split_bf16(float x, __nv_bfloat16& h, __nv_bfloat16& l) {
    h = __float2bfloat16(x);
    l = __float2bfloat16(x - __bfloat162float(h));
}

// ---------------- init / small kernels --------------------------------------
__global__ void init_kernel(int* cnt, float* out) {
    int i = blockIdx.x * blockDim.x + threadIdx.x;
    if (i < NA) cnt[i] = 0;
    if (i < NMOL) out[i] = 0.f;
}

__global__ void embed_kernel(const int* __restrict__ z,
                             const float* __restrict__ embed,
                             float* __restrict__ s,
                             __nv_bfloat16* __restrict__ sh,
                             __nv_bfloat16* __restrict__ sl) {
    int i = blockIdx.x * blockDim.x + threadIdx.x;
    if (i >= NA * 32) return;
    int atom = i >> 5, q = i & 31;
    float4 v = ((const float4*)(embed + (size_t)z[atom] * FF))[q];
    ((float4*)s)[i] = v;
    __nv_bfloat16 h0, h1, h2, h3, l0, l1, l2, l3;
    split_bf16(v.x, h0, l0); split_bf16(v.y, h1, l1);
    split_bf16(v.z, h2, l2); split_bf16(v.w, h3, l3);
    uint2 hp, lp;
    hp.x = ((uint32_t)__bfloat16_as_ushort(h1) << 16) | __bfloat16_as_ushort(h0);
    hp.y = ((uint32_t)__bfloat16_as_ushort(h3) << 16) | __bfloat16_as_ushort(h2);
    lp.x = ((uint32_t)__bfloat16_as_ushort(l1) << 16) | __bfloat16_as_ushort(l0);
    lp.y = ((uint32_t)__bfloat16_as_ushort(l3) << 16) | __bfloat16_as_ushort(l2);
    ((uint2*)sh)[i] = hp;
    ((uint2*)sl)[i] = lp;
}

// one-shot weight prep: fp32 W[K][N] -> bf16 hi/lo at [n][K] (transposed).
// Per-layer blob (elements): w1@0 w2@16384 u@65536 v@81920 a1@98304 a2@131072
// out_w1 @ 540672. Total 557056.
__global__ void wprep_all(const float* __restrict__ msg_w1,
                          const float* __restrict__ msg_w2,
                          const float* __restrict__ upd_u,
                          const float* __restrict__ upd_v,
                          const float* __restrict__ upd_a1,
                          const float* __restrict__ upd_a2,
                          const float* __restrict__ out_w1,
                          __nv_bfloat16* __restrict__ hi,
                          __nv_bfloat16* __restrict__ lo) {
    int i = blockIdx.x * blockDim.x + threadIdx.x;
    if (i >= 557056) return;
    const float* src;
    int K, N, idx, segbase;
    if (i >= 540672) {
        src = out_w1; K = 128; N = 128; idx = i - 540672; segbase = 540672;
    } else {
        int l = i / 180224;
        int r = i - l * 180224;
        if (r < 16384)       { src = msg_w1 + l * 16384; K = 128; N = 128; idx = r;          segbase = l * 180224; }
        else if (r < 65536)  { src = msg_w2 + l * 49152; K = 128; N = 384; idx = r - 16384;  segbase = l * 180224 + 16384; }
        else if (r < 81920)  { src = upd_u  + l * 16384; K = 128; N = 128; idx = r - 65536;  segbase = l * 180224 + 65536; }
        else if (r < 98304)  { src = upd_v  + l * 16384; K = 128; N = 128; idx = r - 81920;  segbase = l * 180224 + 81920; }
        else if (r < 131072) { src = upd_a1 + l * 32768; K = 256; N = 128; idx = r - 98304;  segbase = l * 180224 + 98304; }
        else                 { src = upd_a2 + l * 49152; K = 128; N = 384; idx = r - 131072; segbase = l * 180224 + 131072; }
    }
    int k = idx / N, n = idx - k * N;
    float a = src[idx];
    __nv_bfloat16 h, l2;
    split_bf16(a, h, l2);
    hi[(size_t)segbase + (size_t)n * K + k] = h;
    lo[(size_t)segbase + (size_t)n * K + k] = l2;
}

// ---------------- CSR build + edge geometry --------------------------------
__global__ void count_kernel(const int* __restrict__ dst, int* __restrict__ cnt) {
    int e = blockIdx.x * blockDim.x + threadIdx.x;
    if (e < NE) atomicAdd(&cnt[dst[e]], 1);
}

__global__ void scan_kernel(const int* __restrict__ cnt,
                            int* __restrict__ rowstart,
                            int* __restrict__ cursor) {
    __shared__ int part[1024];
    int t = threadIdx.x;
    int loc[8], ex[8];
    int run = 0;
#pragma unroll
    for (int i = 0; i < 8; i++) {
        loc[i] = cnt[t * 8 + i];
        ex[i]  = run;
        run   += loc[i];
    }
    part[t] = run;
    __syncthreads();
    for (int off = 1; off < 1024; off <<= 1) {
        int v = (t >= off) ? part[t - off] : 0;
        __syncthreads();
        part[t] += v;
        __syncthreads();
    }
    int base = (t > 0) ? part[t - 1] : 0;
#pragma unroll
    for (int i = 0; i < 8; i++) {
        int rs = base + ex[i];
        rowstart[t * 8 + i] = rs;
        cursor[t * 8 + i]   = rs;
    }
    if (t == 1023) rowstart[NA] = part[1023];
}

__global__ void fill_kernel(const int* __restrict__ src,
                            const int* __restrict__ dst,
                            const float* __restrict__ pos,
                            int* __restrict__ cursor,
                            float* __restrict__ egeo,
                            int* __restrict__ esrc) {
    int e = blockIdx.x * blockDim.x + threadIdx.x;
    if (e >= NE) return;
    int sd = src[e], dd = dst[e];
    int p = atomicAdd(&cursor[dd], 1);
    float dx = pos[dd * 3 + 0] - pos[sd * 3 + 0];
    float dy = pos[dd * 3 + 1] - pos[sd * 3 + 1];
    float dz = pos[dd * 3 + 2] - pos[sd * 3 + 2];
    float d  = sqrtf(dx * dx + dy * dy + dz * dz + 1e-8f);
    float inv = 1.f / d;
    float fc = 0.5f * (cosf(PI_F * d / 5.0f) + 1.0f) * (d < 5.0f ? 1.f : 0.f);
    float* g = egeo + (size_t)p * 24;
#pragma unroll
    for (int r = 0; r < RR; r++) {
        float freq = (float)(r + 1) * (PI_F / 5.0f);
        g[r] = sinf(d * freq) * inv * fc;
    }
    g[20] = fc;
    g[21] = dx * inv; g[22] = dy * inv; g[23] = dz * inv;
    esrc[p] = sd;
}

// ---------------- MMA primitives --------------------------------------------
__device__ __forceinline__ void mma16816(float* d, const uint32_t* a, const uint32_t* b) {
    asm volatile(
        "mma.sync.aligned.m16n8k16.row.col.f32.bf16.bf16.f32 "
        "{%0,%1,%2,%3}, {%4,%5,%6,%7}, {%8,%9}, {%0,%1,%2,%3};"
        : "+f"(d[0]), "+f"(d[1]), "+f"(d[2]), "+f"(d[3])
        : "r"(a[0]), "r"(a[1]), "r"(a[2]), "r"(a[3]), "r"(b[0]), "r"(b[1]));
}
__device__ __forceinline__ void ldsm4(uint32_t* r, const __nv_bfloat16* p) {
    uint32_t addr = (uint32_t)__cvta_generic_to_shared(p);
    asm volatile("ldmatrix.sync.aligned.m8n8.x4.shared.b16 {%0,%1,%2,%3}, [%4];"
        : "=r"(r[0]), "=r"(r[1]), "=r"(r[2]), "=r"(r[3]) : "r"(addr));
}

// ---------------- standalone HMMA GEMM (64x64 CTA tile) ---------------------
#define GPAD 72
#define GT_SMEM (4 * 64 * GPAD * 2)

template <bool SILU, bool OSPLIT>
__global__ __launch_bounds__(128)
void gemm_mma(const __nv_bfloat16* __restrict__ Ahi_g,
              const __nv_bfloat16* __restrict__ Alo_g,
              const __nv_bfloat16* __restrict__ Whi,
              const __nv_bfloat16* __restrict__ Wlo,
              const float* __restrict__ bias, float* __restrict__ C,
              __nv_bfloat16* __restrict__ Chi, __nv_bfloat16* __restrict__ Clo,
              int M, int N, int K) {
    extern __shared__ __nv_bfloat16 sm[];
    __nv_bfloat16* Ahi = sm;
    __nv_bfloat16* Alo = sm + 64 * GPAD;
    __nv_bfloat16* Bhi = sm + 2 * 64 * GPAD;
    __nv_bfloat16* Blo = sm + 3 * 64 * GPAD;

    int tid = threadIdx.x, wid = tid >> 5, lane = tid & 31;
    int bm = blockIdx.y << 6, bn = blockIdx.x << 6;
    int wm = (wid & 1) << 5, wn = (wid >> 1) << 5;
    int g = lane >> 2, tg = lane & 3;

    float d[2][4][4];
#pragma unroll
    for (int mt = 0; mt < 2; mt++)
#pragma unroll
        for (int nt = 0; nt < 4; nt++)
#pragma unroll
            for (int q = 0; q < 4; q++) d[mt][nt][q] = 0.f;

    int a_row = (lane & 15), a_kh = (lane >> 4) << 3;
    int b_row = (lane & 7) + ((lane >> 4) << 3), b_kh = ((lane >> 3) & 1) << 3;

    for (int kc = 0; kc < K; kc += 64) {
#pragma unroll
        for (int it = 0; it < 4; it++) {
            int idx = it * 128 + tid;
            int r = idx >> 3, c = (idx & 7) << 3;
            *(uint4*)&Ahi[r * GPAD + c] = *(const uint4*)&Ahi_g[(size_t)(bm + r) * K + kc + c];
            *(uint4*)&Alo[r * GPAD + c] = *(const uint4*)&Alo_g[(size_t)(bm + r) * K + kc + c];
            *(uint4*)&Bhi[r * GPAD + c] = *(const uint4*)&Whi[(size_t)(bn + r) * K + kc + c];
            *(uint4*)&Blo[r * GPAD + c] = *(const uint4*)&Wlo[(size_t)(bn + r) * K + kc + c];
        }
        __syncthreads();

#pragma unroll
        for (int ks = 0; ks < 4; ks++) {
            int k0 = ks * 16;
            uint32_t ah[2][4], al[2][4], bh[2][4], bl[2][4];
#pragma unroll
            for (int mt = 0; mt < 2; mt++) {
                ldsm4(ah[mt], &Ahi[(wm + mt * 16 + a_row) * GPAD + k0 + a_kh]);
                ldsm4(al[mt], &Alo[(wm + mt * 16 + a_row) * GPAD + k0 + a_kh]);
            }
#pragma unroll
            for (int j = 0; j < 2; j++) {
                ldsm4(bh[j], &Bhi[(wn + j * 16 + b_row) * GPAD + k0 + b_kh]);
                ldsm4(bl[j], &Blo[(wn + j * 16 + b_row) * GPAD + k0 + b_kh]);
            }
#pragma unroll
            for (int mt = 0; mt < 2; mt++)
#pragma unroll
                for (int nt = 0; nt < 4; nt++) {
                    const uint32_t* bhp = &bh[nt >> 1][(nt & 1) << 1];
                    const uint32_t* blp = &bl[nt >> 1][(nt & 1) << 1];
                    mma16816(d[mt][nt], ah[mt], bhp);
                    mma16816(d[mt][nt], ah[mt], blp);
                    mma16816(d[mt][nt], al[mt], bhp);
                }
        }
        __syncthreads();
    }

#pragma unroll
    for (int mt = 0; mt < 2; mt++) {
        int row0 = bm + wm + mt * 16 + g;
#pragma unroll
        for (int nt = 0; nt < 4; nt++) {
            int col = bn + wn + nt * 8 + tg * 2;
            float b0 = 0.f, b1 = 0.f;
            if (bias) { b0 = bias[col]; b1 = bias[col + 1]; }
            float x0 = d[mt][nt][0] + b0, x1 = d[mt][nt][1] + b1;
            float x2 = d[mt][nt][2] + b0, x3 = d[mt][nt][3] + b1;
            if (SILU) {
                x0 = x0 / (1.f + __expf(-x0));
                x1 = x1 / (1.f + __expf(-x1));
                x2 = x2 / (1.f + __expf(-x2));
                x3 = x3 / (1.f + __expf(-x3));
            }
            if (OSPLIT) {
                __nv_bfloat16 h0, h1, h2, h3, l0, l1, l2, l3;
                split_bf16(x0, h0, l0); split_bf16(x1, h1, l1);
                split_bf16(x2, h2, l2); split_bf16(x3, h3, l3);
                *(__nv_bfloat162*)&Chi[(size_t)row0 * N + col]       = __nv_bfloat162(h0, h1);
                *(__nv_bfloat162*)&Clo[(size_t)row0 * N + col]       = __nv_bfloat162(l0, l1);
                *(__nv_bfloat162*)&Chi[(size_t)(row0 + 8) * N + col] = __nv_bfloat162(h2, h3);
                *(__nv_bfloat162*)&Clo[(size_t)(row0 + 8) * N + col] = __nv_bfloat162(l2, l3);
            } else {
                *(float2*)&C[(size_t)row0 * N + col]       = make_float2(x0, x1);
                *(float2*)&C[(size_t)(row0 + 8) * N + col] = make_float2(x2, x3);
            }
        }
    }
}

// ---------------- fused 2-layer MLP: C = (silu(A@W1+b1)) @ W2 + b2 ----------
// A pre-split bf16 hi/lo [m][K1]; W1 [128 n][K1]; W2 [N2 n][128].
// CTA = 64 rows, 256 thr (8 warps as 2m x 4n). X1 kept in smem bf16 hi/lo.
// smem layout (bf16 elems): X1h@0 (64*136), X1l@8704, Ah@17408 (64*72),
//   Al@22016, Bh@26624 (128*72), Bl@35840. Total 45056 elems = 90112 B.
#define XGP 136
#define MLP_SMEM (45056 * 2)

__global__ __launch_bounds__(256)
void mlp2_kernel(const __nv_bfloat16* __restrict__ Ahi_g,
                 const __nv_bfloat16* __restrict__ Alo_g,
                 const __nv_bfloat16* __restrict__ W1hi,
                 const __nv_bfloat16* __restrict__ W1lo,
                 const float* __restrict__ b1,
                 const __nv_bfloat16* __restrict__ W2hi,
                 const __nv_bfloat16* __restrict__ W2lo,
                 const float* __restrict__ b2,
                 float* __restrict__ C,
                 int K1, int N2) {
    extern __shared__ __nv_bfloat16 sm[];
    __nv_bfloat16* X1h = sm;
    __nv_bfloat16* X1l = sm + 8704;
    __nv_bfloat16* Ah  = sm + 17408;
    __nv_bfloat16* Al  = sm + 22016;
    __nv_bfloat16* Bh  = sm + 26624;
    __nv_bfloat16* Bl  = sm + 35840;

    int tid = threadIdx.x, wid = tid >> 5, lane = tid & 31;
    int bm = blockIdx.x << 6;
    int wm = (wid & 1) << 5;         // 2 m-warps
    int wn = (wid >> 1) << 5;        // 4 n-warps over 128
    int g = lane >> 2, tg = lane & 3;
    int a_row = (lane & 15), a_kh = (lane >> 4) << 3;
    int b_row = (lane & 7) + ((lane >> 4) << 3), b_kh = ((lane >> 3) & 1) << 3;

    // ---------------- stage 1: X1 = silu(A @ W1 + b1), 64 x 128 -------------
    float d[2][4][4];
#pragma unroll
    for (int mt = 0; mt < 2; mt++)
#pragma unroll
        for (int nt = 0; nt < 4; nt++)
#pragma unroll
            for (int q = 0; q < 4; q++) d[mt][nt][q] = 0.f;

    for (int kc = 0; kc < K1; kc += 64) {
        // stage A 64x64 hi/lo: 512 uint4 per split -> 2 per thread each
#pragma unroll
        for (int it = 0; it < 2; it++) {
            int idx = it * 256 + tid;
            int r = idx >> 3, c = (idx & 7) << 3;
            *(uint4*)&Ah[r * GPAD + c] = *(const uint4*)&Ahi_g[(size_t)(bm + r) * K1 + kc + c];
            *(uint4*)&Al[r * GPAD + c] = *(const uint4*)&Alo_g[(size_t)(bm + r) * K1 + kc + c];
        }
        // stage W1 128x64 hi/lo: 1024 uint4 per split -> 4 per thread each
#pragma unroll
        for (int it = 0; it < 4; it++) {
            int idx = it * 256 + tid;
            int r = idx >> 3, c = (idx & 7) << 3;
            *(uint4*)&Bh[r * GPAD + c] = *(const uint4*)&W1hi[(size_t)r * K1 + kc + c];
            *(uint4*)&Bl[r * GPAD + c] = *(const uint4*)&W1lo[(size_t)r * K1 + kc + c];
        }
        __syncthreads();
#pragma unroll
        for (int ks = 0; ks < 4; ks++) {
            int k0 = ks * 16;
            uint32_t ah[2][4], al[2][4], bh[2][4], bl[2][4];
#pragma unroll
            for (int mt = 0; mt < 2; mt++) {
                ldsm4(ah[mt], &Ah[(wm + mt * 16 + a_row) * GPAD + k0 + a_kh]);
                ldsm4(al[mt], &Al[(wm + mt * 16 + a_row) * GPAD + k0 + a_kh]);
            }
#pragma unroll
            for (int j = 0; j < 2; j++) {
                ldsm4(bh[j], &Bh[(wn + j * 16 + b_row) * GPAD + k0 + b_kh]);
                ldsm4(bl[j], &Bl[(wn + j * 16 + b_row) * GPAD + k0 + b_kh]);
            }
#pragma unroll
            for (int mt = 0; mt < 2; mt++)
#pragma unroll
                for (int nt = 0; nt < 4; nt++) {
                    const uint32_t* bhp = &bh[nt >> 1][(nt & 1) << 1];
                    const uint32_t* blp = &bl[nt >> 1][(nt & 1) << 1];
                    mma16816(d[mt][nt], ah[mt], bhp);
                    mma16816(d[mt][nt], ah[mt], blp);
                    mma16816(d[mt][nt], al[mt], bhp);
                }
        }
        __syncthreads();
    }

    // bias + silu + split -> X1 smem (bf16 hi/lo)
#pragma unroll
    for (int mt = 0; mt < 2; mt++) {
        int r0 = wm + mt * 16 + g;
#pragma unroll
        for (int nt = 0; nt < 4; nt++) {
            int col = wn + nt * 8 + tg * 2;
            float b0 = b1[col], bb = b1[col + 1];
            float x0 = d[mt][nt][0] + b0, x1 = d[mt][nt][1] + bb;
            float x2 = d[mt][nt][2] + b0, x3 = d[mt][nt][3] + bb;
            x0 = x0 / (1.f + __expf(-x0));
            x1 = x1 / (1.f + __expf(-x1));
            x2 = x2 / (1.f + __expf(-x2));
            x3 = x3 / (1.f + __expf(-x3));
            __nv_bfloat16 h0, h1, h2, h3, l0, l1, l2, l3;
            split_bf16(x0, h0, l0); split_bf16(x1, h1, l1);
            split_bf16(x2, h2, l2); split_bf16(x3, h3, l3);
            *(__nv_bfloat162*)&X1h[r0 * XGP + col]       = __nv_bfloat162(h0, h1);
            *(__nv_bfloat162*)&X1l[r0 * XGP + col]       = __nv_bfloat162(l0, l1);
            *(__nv_bfloat162*)&X1h[(r0 + 8) * XGP + col] = __nv_bfloat162(h2, h3);
            *(__nv_bfloat162*)&X1l[(r0 + 8) * XGP + col] = __nv_bfloat162(l2, l3);
        }
    }
    __syncthreads();

    // ---------------- stage 2: C = X1 @ W2 + b2, 64 x N2 --------------------
    for (int nc = 0; nc < N2; nc += 128) {
        float e[2][4][4];
#pragma unroll
        for (int mt = 0; mt < 2; mt++)
#pragma unroll
            for (int nt = 0; nt < 4; nt++)
#pragma unroll
                for (int q = 0; q < 4; q++) e[mt][nt][q] = 0.f;

        for (int kc2 = 0; kc2 < 2; kc2++) {
            __syncthreads();   // protect B bufs from prior readers
#pragma unroll
            for (int it = 0; it < 4; it++) {
                int idx = it * 256 + tid;
                int r = idx >> 3, c = (idx & 7) << 3;
                *(uint4*)&Bh[r * GPAD + c] = *(const uint4*)&W2hi[(size_t)(nc + r) * 128 + kc2 * 64 + c];
                *(uint4*)&Bl[r * GPAD + c] = *(const uint4*)&W2lo[(size_t)(nc + r) * 128 + kc2 * 64 + c];
            }
            __syncthreads();
#pragma unroll
            for (int ks = 0; ks < 4; ks++) {
                int k0 = ks * 16;
                int ka = kc2 * 64 + k0;
                uint32_t ah[2][4], al[2][4], bh[2][4], bl[2][4];
#pragma unroll
                for (int mt = 0; mt < 2; mt++) {
                    ldsm4(ah[mt], &X1h[(wm + mt * 16 + a_row) * XGP + ka + a_kh]);
                    ldsm4(al[mt], &X1l[(wm + mt * 16 + a_row) * XGP + ka + a_kh]);
                }
#pragma unroll
                for (int j = 0; j < 2; j++) {
                    ldsm4(bh[j], &Bh[(wn + j * 16 + b_row) * GPAD + k0 + b_kh]);
                    ldsm4(bl[j], &Bl[(wn + j * 16 + b_row) * GPAD + k0 + b_kh]);
                }
#pragma unroll
                for (int mt = 0; mt < 2; mt++)
#pragma unroll
                    for (int nt = 0; nt < 4; nt++) {
                        const uint32_t* bhp = &bh[nt >> 1][(nt & 1) << 1];
                        const uint32_t* blp = &bl[nt >> 1][(nt & 1) << 1];
                        mma16816(e[mt][nt], ah[mt], bhp);
                        mma16816(e[mt][nt], ah[mt], blp);
                        mma16816(e[mt][nt], al[mt], bhp);
                    }
            }
        }
        // epilogue for this n-chunk (fp32 out, no activation)
#pragma unroll
        for (int mt = 0; mt < 2; mt++) {
            int row0 = bm + wm + mt * 16 + g;
#pragma unroll
            for (int nt = 0; nt < 4; nt++) {
                int col = nc + wn + nt * 8 + tg * 2;
                float b0 = b2[col], bb = b2[col + 1];
                *(float2*)&C[(size_t)row0 * N2 + col] =
                    make_float2(e[mt][nt][0] + b0, e[mt][nt][1] + bb);
                *(float2*)&C[(size_t)(row0 + 8) * N2 + col] =
                    make_float2(e[mt][nt][2] + b0, e[mt][nt][3] + bb);
            }
        }
    }
}

// ---------------- message pass (CSR gather, f32x2 feature pairs) ------------
#define APB 4
#define CH  32
template <bool FIRST>
__global__ __launch_bounds__(64)
void msg_kernel(const float* __restrict__ phi, const float* __restrict__ vin,
                float* __restrict__ s, float* __restrict__ vout,
                __nv_bfloat16* __restrict__ vbh, __nv_bfloat16* __restrict__ vbl,
                const float* __restrict__ rbfW, const float* __restrict__ rbfB,
                const float* __restrict__ egeo, const int* __restrict__ esrc,
                const int* __restrict__ rowstart) {
    int t = threadIdx.x;                  // owns feature pair (2t, 2t+1)
    int f2 = t * 2;
    float2 w1[RR], w2[RR], w3[RR];
#pragma unroll
    for (int r = 0; r < RR; r++) {
        w1[r] = *(const float2*)&rbfW[r * 384 + f2];
        if (!FIRST) w2[r] = *(const float2*)&rbfW[r * 384 + 128 + f2];
        w3[r] = *(const float2*)&rbfW[r * 384 + 256 + f2];
    }
    float2 b1 = *(const float2*)&rbfB[f2];
    float2 b2 = FIRST ? make_float2(0.f, 0.f) : *(const float2*)&rbfB[128 + f2];
    float2 b3 = *(const float2*)&rbfB[256 + f2];

    __shared__ float2 sG[CH][24];   // per-edge scalars duplicated {v,v}
    __shared__ int    sS[CH];

    int a0 = blockIdx.x * APB;
    for (int a = a0; a < a0 + APB; a++) {
        int beg = rowstart[a], end = rowstart[a + 1];
        float2 ds  = make_float2(0.f, 0.f);
        float2 dv0 = ds, dv1 = ds, dv2 = ds;
        for (int c0 = beg; c0 < end; c0 += CH) {
            int nc = min(CH, end - c0);
            __syncthreads();
            for (int i = t; i < nc * 24; i += 64) {
                float v = egeo[(size_t)c0 * 24 + i];
                sG[i / 24][i % 24] = make_float2(v, v);
            }
            if (t < nc) sS[t] = esrc[c0 + t];
            __syncthreads();
            for (int k = 0; k < nc; k++) {
                const float2* gk = sG[k];
                int src = sS[k];
                const float* pb = phi + (size_t)src * 384;
                float2 p0 = *(const float2*)(pb + f2);
                float2 p1, p2;
                p2 = *(const float2*)(pb + 256 + f2);
                float2 v0, v1, v2;
                if (!FIRST) {
                    p1 = *(const float2*)(pb + 128 + f2);
                    const float* vb = vin + (size_t)src * 384;
                    v0 = *(const float2*)(vb + f2);
                    v1 = *(const float2*)(vb + 128 + f2);
                    v2 = *(const float2*)(vb + 256 + f2);
                }
                float2 fc = gk[20];
                float2 wf1 = fmul2(fc, b1);
                float2 wf2 = FIRST ? make_float2(0.f, 0.f) : fmul2(fc, b2);
                float2 wf3 = fmul2(fc, b3);
#pragma unroll
                for (int r = 0; r < RR; r++) {
                    float2 rb = gk[r];
                    wf1 = ffma2(rb, w1[r], wf1);
                    if (!FIRST) wf2 = ffma2(rb, w2[r], wf2);
                    wf3 = ffma2(rb, w3[r], wf3);
                }
                ds = ffma2(p0, wf1, ds);
                float2 dvs = fmul2(p2, wf3);
                dv0 = ffma2(gk[21], dvs, dv0);
                dv1 = ffma2(gk[22], dvs, dv1);
                dv2 = ffma2(gk[23], dvs, dv2);
                if (!FIRST) {
                    float2 dvv = fmul2(p1, wf2);
                    dv0 = ffma2(v0, dvv, dv0);
                    dv1 = ffma2(v1, dvv, dv1);
                    dv2 = ffma2(v2, dvv, dv2);
                }
            }
        }
        size_t sa = (size_t)a * 128 + f2;
        size_t va = (size_t)a * 384 + f2;
        *(float2*)&s[sa] = fadd2(*(const float2*)&s[sa], ds);
        float2 o0, o1, o2;
        if (FIRST) {
            o0 = dv0; o1 = dv1; o2 = dv2;
        } else {
            o0 = fadd2(*(const float2*)&vin[va],       dv0);
            o1 = fadd2(*(const float2*)&vin[va + 128], dv1);
            o2 = fadd2(*(const float2*)&vin[va + 256], dv2);
        }
        *(float2*)&vout[va]       = o0;
        *(float2*)&vout[va + 128] = o1;
        *(float2*)&vout[va + 256] = o2;
        __nv_bfloat16 h0, h1, l0, l1;
        split_bf16(o0.x, h0, l0); split_bf16(o0.y, h1, l1);
        *(__nv_bfloat162*)&vbh[va]       = __nv_bfloat162(h0, h1);
        *(__nv_bfloat162*)&vbl[va]       = __nv_bfloat162(l0, l1);
        split_bf16(o1.x, h0, l0); split_bf16(o1.y, h1, l1);
        *(__nv_bfloat162*)&vbh[va + 128] = __nv_bfloat162(h0, h1);
        *(__nv_bfloat162*)&vbl[va + 128] = __nv_bfloat162(l0, l1);
        split_bf16(o2.x, h0, l0); split_bf16(o2.y, h1, l1);
        *(__nv_bfloat162*)&vbh[va + 256] = __nv_bfloat162(h0, h1);
        *(__nv_bfloat162*)&vbl[va + 256] = __nv_bfloat162(l0, l1);
    }
}

// ---------------- per-atom update pieces ------------------------------------
// uvv layout: [atom*3 + c][256] with cols 0..127 = uv, 128..255 = vv
__global__ void cat_kernel(const float* __restrict__ s, const float* __restrict__ uvv,
                           __nv_bfloat16* __restrict__ cth,
                           __nv_bfloat16* __restrict__ ctl) {
    int i = blockIdx.x * blockDim.x + threadIdx.x;
    if (i >= NA * FF) return;
    int atom = i >> 7, f = i & 127;
    size_t base = (size_t)atom * 3 * 256 + 128 + f;
    float x0 = uvv[base], x1 = uvv[base + 256], x2 = uvv[base + 512];
    float n = sqrtf(x0 * x0 + x1 * x1 + x2 * x2 + 1e-8f);
    __nv_bfloat16 h, l;
    size_t c0 = (size_t)atom * 256 + f;
    split_bf16(s[i], h, l);
    cth[c0] = h; ctl[c0] = l;
    split_bf16(n, h, l);
    cth[c0 + 128] = h; ctl[c0 + 128] = l;
}

__global__ void upd_kernel(const float* __restrict__ uvv,
                           const float* __restrict__ a,
                           float* __restrict__ s,
                           __nv_bfloat16* __restrict__ sh, __nv_bfloat16* __restrict__ sl,
                           const float* __restrict__ vB, float* __restrict__ vA) {
    int i = blockIdx.x * blockDim.x + threadIdx.x;
    if (i >= NA * FF) return;
    int atom = i >> 7, f = i & 127;
    size_t ub = (size_t)atom * 3 * 256 + f;
    float u0 = uvv[ub],       u1 = uvv[ub + 256], u2 = uvv[ub + 512];
    float x0 = uvv[ub + 128], x1 = uvv[ub + 384], x2 = uvv[ub + 640];
    float dot = u0 * x0 + u1 * x1 + u2 * x2;
    size_t off = (size_t)atom * 384;
    float a_vv = a[off + f], a_sv = a[off + 128 + f], a_ss = a[off + 256 + f];
    float sn = s[i] + a_ss + a_sv * dot;
    s[i] = sn;
    __nv_bfloat16 h, l;
    split_bf16(sn, h, l);
    sh[i] = h; sl[i] = l;
    vA[off + f]       = vB[off + f]       + a_vv * u0;
    vA[off + 128 + f] = vB[off + 128 + f] + a_vv * u1;
    vA[off + 256 + f] = vB[off + 256 + f] + a_vv * u2;
}

// ---------------- readout: GEMV + molecule segment sum ---------------------
__global__ void out2_kernel(const float* __restrict__ h, const float* __restrict__ w2,
                            const float* __restrict__ b2, const int* __restrict__ mol,
                            float* __restrict__ out) {
    int gw = (blockIdx.x * blockDim.x + threadIdx.x) >> 5;
    int lane = threadIdx.x & 31;
    if (gw >= NA) return;
    const float* hp = h + (size_t)gw * FF;
    float sum = 0.f;
#pragma unroll
    for (int i = lane; i < FF; i += 32) sum = fmaf(hp[i], w2[i], sum);
#pragma unroll
    for (int o = 16; o; o >>= 1) sum += __shfl_down_sync(0xffffffffu, sum, o);
    if (lane == 0) atomicAdd(&out[mol[gw]], sum + b2[0]);
}

// ---------------- host-side launch ------------------------------------------
static float* symf(const void* sym) {
    void* p = nullptr;
    cudaGetSymbolAddress(&p, sym);
    return (float*)p;
}
static int* symi(const void* sym) {
    void* p = nullptr;
    cudaGetSymbolAddress(&p, sym);
    return (int*)p;
}
static __nv_bfloat16* symb(const void* sym) {
    void* p = nullptr;
    cudaGetSymbolAddress(&p, sym);
    return (__nv_bfloat16*)p;
}

extern "C" void kernel_launch(void* const* d_in, const int* in_sizes, int n_in,
                              void* d_out, int out_size) {
    const int*   z        = (const int*)  d_in[0];
    const float* pos      = (const float*)d_in[1];
    const int*   edge_src = (const int*)  d_in[2];
    const int*   edge_dst = (const int*)  d_in[3];
    const int*   mol_idx  = (const int*)  d_in[4];
    const float* embed    = (const float*)d_in[5];
    const float* msg_w1   = (const float*)d_in[6];
    const float* msg_b1   = (const float*)d_in[7];
    const float* msg_w2   = (const float*)d_in[8];
    const float* msg_b2   = (const float*)d_in[9];
    const float* rbf_w    = (const float*)d_in[10];
    const float* rbf_b    = (const float*)d_in[11];
    const float* upd_u    = (const float*)d_in[12];
    const float* upd_v    = (const float*)d_in[13];
    const float* upd_a1   = (const float*)d_in[14];
    const float* upd_a1b  = (const float*)d_in[15];
    const float* upd_a2   = (const float*)d_in[16];
    const float* upd_a2b  = (const float*)d_in[17];
    const float* out_w1   = (const float*)d_in[18];
    const float* out_b1   = (const float*)d_in[19];
    const float* out_w2   = (const float*)d_in[20];
    const float* out_b2   = (const float*)d_in[21];
    float* out = (float*)d_out;

    float* s    = symf(g_s);
    float* vA   = symf(g_vA);
    float* vB   = symf(g_vB);
    float* h    = symf(g_h);
    float* phi  = symf(g_phi);
    float* uvv  = symf(g_uvv);
    float* a    = symf(g_a);
    float* egeo = symf(g_egeo);
    int* esrc   = symi(g_esrc);
    int* rowst  = symi(g_rowstart);
    int* cursor = symi(g_cursor);
    int* count  = symi(g_count);
    __nv_bfloat16* whi = symb(g_whi);
    __nv_bfloat16* wlo = symb(g_wlo);
    __nv_bfloat16* sh  = symb(g_sh),  *sl  = symb(g_sl);
    __nv_bfloat16* vbh = symb(g_vbh), *vbl = symb(g_vbl);
    __nv_bfloat16* cth = symb(g_cth), *ctl = symb(g_ctl);

    cudaFuncSetAttribute(gemm_mma<true,  false>, cudaFuncAttributeMaxDynamicSharedMemorySize, GT_SMEM);
    cudaFuncSetAttribute(gemm_mma<false, false>, cudaFuncAttributeMaxDynamicSharedMemorySize, GT_SMEM);
    cudaFuncSetAttribute(mlp2_kernel, cudaFuncAttributeMaxDynamicSharedMemorySize, MLP_SMEM);

    // prelude (launch index 3 gets profiled -> first mlp2)
    init_kernel<<<(NA + 255) / 256, 256>>>(count, out);
    embed_kernel<<<(NA * 32 + 255) / 256, 256>>>(z, embed, s, sh, sl);
    wprep_all<<<(557056 + 255) / 256, 256>>>(msg_w1, msg_w2, upd_u, upd_v,
                                             upd_a1, upd_a2, out_w1, whi, wlo);

    bool csr_built = false;
    for (int l = 0; l < LL; l++) {
        size_t LB = (size_t)l * 180224;
        const float* bb1 = msg_b1  + (size_t)l * FF;
        const float* bb2 = msg_b2  + (size_t)l * 3 * FF;
        const float* rw  = rbf_w   + (size_t)l * RR * 3 * FF;
        const float* rb  = rbf_b   + (size_t)l * 3 * FF;
        const float* a1b = upd_a1b + (size_t)l * FF;
        const float* a2b = upd_a2b + (size_t)l * 3 * FF;

        // fused s -> h -> phi
        mlp2_kernel<<<NA / 64, 256, MLP_SMEM>>>(sh, sl,
            whi + LB, wlo + LB, bb1,
            whi + LB + 16384, wlo + LB + 16384, bb2,
            phi, 128, 384);
        if (!csr_built) {
            count_kernel<<<(NE + 255) / 256, 256>>>(edge_dst, count);
            scan_kernel<<<1, 1024>>>(count, rowst, cursor);
            fill_kernel<<<(NE + 255) / 256, 256>>>(edge_src, edge_dst, pos, cursor, egeo, esrc);
            csr_built = true;
        }
        if (l == 0)
            msg_kernel<true ><<<NA / APB, 64>>>(phi, vA, s, vB, vbh, vbl, rw, rb, egeo, esrc, rowst);
        else
            msg_kernel<false><<<NA / APB, 64>>>(phi, vA, s, vB, vbh, vbl, rw, rb, egeo, esrc, rowst);
        gemm_mma<false, false><<<dim3(4, 384), 128, GT_SMEM>>>(vbh, vbl,
            whi + LB + 65536, wlo + LB + 65536, nullptr, uvv, nullptr, nullptr, NA * 3, 256, 128);
        cat_kernel<<<(NA * FF + 255) / 256, 256>>>(s, uvv, cth, ctl);
        // fused cat -> ah -> a
        mlp2_kernel<<<NA / 64, 256, MLP_SMEM>>>(cth, ctl,
            whi + LB + 98304, wlo + LB + 98304, a1b,
            whi + LB + 131072, wlo + LB + 131072, a2b,
            a, 256, 384);
        upd_kernel<<<(NA * FF + 255) / 256, 256>>>(uvv, a, s, sh, sl, vB, vA);
    }

    gemm_mma<true, false><<<dim3(2, 128), 128, GT_SMEM>>>(sh, sl,
        whi + 540672, wlo + 540672, out_b1, h, nullptr, nullptr, NA, 128, 128);
    out2_kernel<<<NA * 32 / 256, 256>>>(h, out_w2, out_b2, mol_idx, out);
}

// round 9
// speedup vs baseline: 1.0153x; 1.0153x over previous
#include <cuda_runtime.h>
#include <cuda_bf16.h>
#include <math.h>
#include <stdint.h>

#define NA   8192
#define NE   262144
#define NMOL 128
#define FF   128
#define RR   20
#define LL   3
#define PI_F 3.14159265358979f

// ---------------- scratch (device globals; no runtime alloc allowed) -------
__device__ float g_s  [NA * FF];
__device__ float g_vA [NA * 3 * FF];
__device__ float g_vB [NA * 3 * FF];
__device__ float g_h  [NA * FF];
__device__ float g_phi[NA * 3 * FF];
__device__ float g_uvv[NA * 3 * 2 * FF];      // fused [atom*3][256]: uv | vv
__device__ float g_a  [NA * 3 * FF];
__device__ float g_egeo[NE * 24];             // per sorted edge: rbf*fc[20], fc, unit[3]
__device__ int   g_esrc[NE];
__device__ int   g_rowstart[NA + 1];
__device__ int   g_cursor[NA];
__device__ int   g_count[NA];
// bf16 hi/lo weight blobs, N-major [n][k]
#define WBLOB_ELEMS (34 * 16384)
__device__ __nv_bfloat16 g_whi[WBLOB_ELEMS];
__device__ __nv_bfloat16 g_wlo[WBLOB_ELEMS];
// bf16 hi/lo activation (A-operand) arrays, k-major rows
__device__ __nv_bfloat16 g_sh [NA * FF],     g_sl [NA * FF];
__device__ __nv_bfloat16 g_vbh[NA * 3 * FF], g_vbl[NA * 3 * FF];
__device__ __nv_bfloat16 g_cth[NA * 2 * FF], g_ctl[NA * 2 * FF];

// ---------------- packed f32x2 helpers --------------------------------------
__device__ __forceinline__ float2 ffma2(float2 a, float2 b, float2 c) {
    float2 d;
    asm("fma.rn.f32x2 %0, %1, %2, %3;"
        : "=l"(*reinterpret_cast<unsigned long long*>(&d))
        : "l"(*reinterpret_cast<unsigned long long*>(&a)),
          "l"(*reinterpret_cast<unsigned long long*>(&b)),
          "l"(*reinterpret_cast<unsigned long long*>(&c)));
    return d;
}
__device__ __forceinline__ float2 fmul2(float2 a, float2 b) {
    float2 d;
    asm("mul.rn.f32x2 %0, %1, %2;"
        : "=l"(*reinterpret_cast<unsigned long long*>(&d))
        : "l"(*reinterpret_cast<unsigned long long*>(&a)),
          "l"(*reinterpret_cast<unsigned long long*>(&b)));
    return d;
}
__device__ __forceinline__ float2 fadd2(float2 a, float2 b) {
    float2 d;
    asm("add.rn.f32x2 %0, %1, %2;"
        : "=l"(*reinterpret_cast<unsigned long long*>(&d))
        : "l"(*reinterpret_cast<unsigned long long*>(&a)),
          "l"(*reinterpret_cast<unsigned long long*>(&b)));
    return d;
}
__device__ __forceinline__ void split_bf16(float x, __nv_bfloat16& h, __nv_bfloat16& l) {
    h = __float2bfloat16(x);
    l = __float2bfloat16(x - __bfloat162float(h));
}

// ---------------- init / small kernels --------------------------------------
__global__ void embed_kernel(const int* __restrict__ z,
                             const float* __restrict__ embed,
                             float* __restrict__ s,
                             __nv_bfloat16* __restrict__ sh,
                             __nv_bfloat16* __restrict__ sl) {
    int i = blockIdx.x * blockDim.x + threadIdx.x;
    if (i >= NA * 32) return;
    int atom = i >> 5, q = i & 31;
    float4 v = ((const float4*)(embed + (size_t)z[atom] * FF))[q];
    ((float4*)s)[i] = v;
    __nv_bfloat16 h0, h1, h2, h3, l0, l1, l2, l3;
    split_bf16(v.x, h0, l0); split_bf16(v.y, h1, l1);
    split_bf16(v.z, h2, l2); split_bf16(v.w, h3, l3);
    uint2 hp, lp;
    hp.x = ((uint32_t)__bfloat16_as_ushort(h1) << 16) | __bfloat16_as_ushort(h0);
    hp.y = ((uint32_t)__bfloat16_as_ushort(h3) << 16) | __bfloat16_as_ushort(h2);
    lp.x = ((uint32_t)__bfloat16_as_ushort(l1) << 16) | __bfloat16_as_ushort(l0);
    lp.y = ((uint32_t)__bfloat16_as_ushort(l3) << 16) | __bfloat16_as_ushort(l2);
    ((uint2*)sh)[i] = hp;
    ((uint2*)sl)[i] = lp;
}

// one-shot weight prep (+ init of count/out): fp32 W[K][N] -> bf16 hi/lo [n][K].
// Per-layer blob (elements): w1@0 w2@16384 u@65536 v@81920 a1@98304 a2@131072
// out_w1 @ 540672. Total 557056.
__global__ void wprep_all(const float* __restrict__ msg_w1,
                          const float* __restrict__ msg_w2,
                          const float* __restrict__ upd_u,
                          const float* __restrict__ upd_v,
                          const float* __restrict__ upd_a1,
                          const float* __restrict__ upd_a2,
                          const float* __restrict__ out_w1,
                          __nv_bfloat16* __restrict__ hi,
                          __nv_bfloat16* __restrict__ lo,
                          int* __restrict__ cnt, float* __restrict__ outp) {
    int i = blockIdx.x * blockDim.x + threadIdx.x;
    if (i < NA) cnt[i] = 0;
    if (i < NMOL) outp[i] = 0.f;
    if (i >= 557056) return;
    const float* src;
    int K, N, idx, segbase;
    if (i >= 540672) {
        src = out_w1; K = 128; N = 128; idx = i - 540672; segbase = 540672;
    } else {
        int l = i / 180224;
        int r = i - l * 180224;
        if (r < 16384)       { src = msg_w1 + l * 16384; K = 128; N = 128; idx = r;          segbase = l * 180224; }
        else if (r < 65536)  { src = msg_w2 + l * 49152; K = 128; N = 384; idx = r - 16384;  segbase = l * 180224 + 16384; }
        else if (r < 81920)  { src = upd_u  + l * 16384; K = 128; N = 128; idx = r - 65536;  segbase = l * 180224 + 65536; }
        else if (r < 98304)  { src = upd_v  + l * 16384; K = 128; N = 128; idx = r - 81920;  segbase = l * 180224 + 81920; }
        else if (r < 131072) { src = upd_a1 + l * 32768; K = 256; N = 128; idx = r - 98304;  segbase = l * 180224 + 98304; }
        else                 { src = upd_a2 + l * 49152; K = 128; N = 384; idx = r - 131072; segbase = l * 180224 + 131072; }
    }
    int k = idx / N, n = idx - k * N;
    float a = src[idx];
    __nv_bfloat16 h, l2;
    split_bf16(a, h, l2);
    hi[(size_t)segbase + (size_t)n * K + k] = h;
    lo[(size_t)segbase + (size_t)n * K + k] = l2;
}

// ---------------- CSR build + edge geometry --------------------------------
__global__ void count_kernel(const int* __restrict__ dst, int* __restrict__ cnt) {
    int e = blockIdx.x * blockDim.x + threadIdx.x;
    if (e < NE) atomicAdd(&cnt[dst[e]], 1);
}

__global__ void scan_kernel(const int* __restrict__ cnt,
                            int* __restrict__ rowstart,
                            int* __restrict__ cursor) {
    __shared__ int part[1024];
    int t = threadIdx.x;
    int loc[8], ex[8];
    int run = 0;
#pragma unroll
    for (int i = 0; i < 8; i++) {
        loc[i] = cnt[t * 8 + i];
        ex[i]  = run;
        run   += loc[i];
    }
    part[t] = run;
    __syncthreads();
    for (int off = 1; off < 1024; off <<= 1) {
        int v = (t >= off) ? part[t - off] : 0;
        __syncthreads();
        part[t] += v;
        __syncthreads();
    }
    int base = (t > 0) ? part[t - 1] : 0;
#pragma unroll
    for (int i = 0; i < 8; i++) {
        int rs = base + ex[i];
        rowstart[t * 8 + i] = rs;
        cursor[t * 8 + i]   = rs;
    }
    if (t == 1023) rowstart[NA] = part[1023];
}

__global__ void fill_kernel(const int* __restrict__ src,
                            const int* __restrict__ dst,
                            const float* __restrict__ pos,
                            int* __restrict__ cursor,
                            float* __restrict__ egeo,
                            int* __restrict__ esrc) {
    int e = blockIdx.x * blockDim.x + threadIdx.x;
    if (e >= NE) return;
    int sd = src[e], dd = dst[e];
    int p = atomicAdd(&cursor[dd], 1);
    float dx = pos[dd * 3 + 0] - pos[sd * 3 + 0];
    float dy = pos[dd * 3 + 1] - pos[sd * 3 + 1];
    float dz = pos[dd * 3 + 2] - pos[sd * 3 + 2];
    float d  = sqrtf(dx * dx + dy * dy + dz * dz + 1e-8f);
    float inv = 1.f / d;
    float fc = 0.5f * (cosf(PI_F * d / 5.0f) + 1.0f) * (d < 5.0f ? 1.f : 0.f);
    float* g = egeo + (size_t)p * 24;
#pragma unroll
    for (int r = 0; r < RR; r++) {
        float freq = (float)(r + 1) * (PI_F / 5.0f);
        g[r] = sinf(d * freq) * inv * fc;
    }
    g[20] = fc;
    g[21] = dx * inv; g[22] = dy * inv; g[23] = dz * inv;
    esrc[p] = sd;
}

// ---------------- MMA primitives --------------------------------------------
__device__ __forceinline__ void mma16816(float* d, const uint32_t* a, const uint32_t* b) {
    asm volatile(
        "mma.sync.aligned.m16n8k16.row.col.f32.bf16.bf16.f32 "
        "{%0,%1,%2,%3}, {%4,%5,%6,%7}, {%8,%9}, {%0,%1,%2,%3};"
        : "+f"(d[0]), "+f"(d[1]), "+f"(d[2]), "+f"(d[3])
        : "r"(a[0]), "r"(a[1]), "r"(a[2]), "r"(a[3]), "r"(b[0]), "r"(b[1]));
}
__device__ __forceinline__ void ldsm4(uint32_t* r, const __nv_bfloat16* p) {
    uint32_t addr = (uint32_t)__cvta_generic_to_shared(p);
    asm volatile("ldmatrix.sync.aligned.m8n8.x4.shared.b16 {%0,%1,%2,%3}, [%4];"
        : "=r"(r[0]), "=r"(r[1]), "=r"(r[2]), "=r"(r[3]) : "r"(addr));
}

// ---------------- standalone HMMA GEMM (64x64 CTA tile) ---------------------
#define GPAD 72
#define GT_SMEM (4 * 64 * GPAD * 2)

template <bool SILU, bool OSPLIT>
__global__ __launch_bounds__(128)
void gemm_mma(const __nv_bfloat16* __restrict__ Ahi_g,
              const __nv_bfloat16* __restrict__ Alo_g,
              const __nv_bfloat16* __restrict__ Whi,
              const __nv_bfloat16* __restrict__ Wlo,
              const float* __restrict__ bias, float* __restrict__ C,
              __nv_bfloat16* __restrict__ Chi, __nv_bfloat16* __restrict__ Clo,
              int M, int N, int K) {
    extern __shared__ __nv_bfloat16 sm[];
    __nv_bfloat16* Ahi = sm;
    __nv_bfloat16* Alo = sm + 64 * GPAD;
    __nv_bfloat16* Bhi = sm + 2 * 64 * GPAD;
    __nv_bfloat16* Blo = sm + 3 * 64 * GPAD;

    int tid = threadIdx.x, wid = tid >> 5, lane = tid & 31;
    int bm = blockIdx.y << 6, bn = blockIdx.x << 6;
    int wm = (wid & 1) << 5, wn = (wid >> 1) << 5;
    int g = lane >> 2, tg = lane & 3;

    float d[2][4][4];
#pragma unroll
    for (int mt = 0; mt < 2; mt++)
#pragma unroll
        for (int nt = 0; nt < 4; nt++)
#pragma unroll
            for (int q = 0; q < 4; q++) d[mt][nt][q] = 0.f;

    int a_row = (lane & 15), a_kh = (lane >> 4) << 3;
    int b_row = (lane & 7) + ((lane >> 4) << 3), b_kh = ((lane >> 3) & 1) << 3;

    for (int kc = 0; kc < K; kc += 64) {
#pragma unroll
        for (int it = 0; it < 4; it++) {
            int idx = it * 128 + tid;
            int r = idx >> 3, c = (idx & 7) << 3;
            *(uint4*)&Ahi[r * GPAD + c] = *(const uint4*)&Ahi_g[(size_t)(bm + r) * K + kc + c];
            *(uint4*)&Alo[r * GPAD + c] = *(const uint4*)&Alo_g[(size_t)(bm + r) * K + kc + c];
            *(uint4*)&Bhi[r * GPAD + c] = *(const uint4*)&Whi[(size_t)(bn + r) * K + kc + c];
            *(uint4*)&Blo[r * GPAD + c] = *(const uint4*)&Wlo[(size_t)(bn + r) * K + kc + c];
        }
        __syncthreads();

#pragma unroll
        for (int ks = 0; ks < 4; ks++) {
            int k0 = ks * 16;
            uint32_t ah[2][4], al[2][4], bh[2][4], bl[2][4];
#pragma unroll
            for (int mt = 0; mt < 2; mt++) {
                ldsm4(ah[mt], &Ahi[(wm + mt * 16 + a_row) * GPAD + k0 + a_kh]);
                ldsm4(al[mt], &Alo[(wm + mt * 16 + a_row) * GPAD + k0 + a_kh]);
            }
#pragma unroll
            for (int j = 0; j < 2; j++) {
                ldsm4(bh[j], &Bhi[(wn + j * 16 + b_row) * GPAD + k0 + b_kh]);
                ldsm4(bl[j], &Blo[(wn + j * 16 + b_row) * GPAD + k0 + b_kh]);
            }
#pragma unroll
            for (int mt = 0; mt < 2; mt++)
#pragma unroll
                for (int nt = 0; nt < 4; nt++) {
                    const uint32_t* bhp = &bh[nt >> 1][(nt & 1) << 1];
                    const uint32_t* blp = &bl[nt >> 1][(nt & 1) << 1];
                    mma16816(d[mt][nt], ah[mt], bhp);
                    mma16816(d[mt][nt], ah[mt], blp);
                    mma16816(d[mt][nt], al[mt], bhp);
                }
        }
        __syncthreads();
    }

#pragma unroll
    for (int mt = 0; mt < 2; mt++) {
        int row0 = bm + wm + mt * 16 + g;
#pragma unroll
        for (int nt = 0; nt < 4; nt++) {
            int col = bn + wn + nt * 8 + tg * 2;
            float b0 = 0.f, b1 = 0.f;
            if (bias) { b0 = bias[col]; b1 = bias[col + 1]; }
            float x0 = d[mt][nt][0] + b0, x1 = d[mt][nt][1] + b1;
            float x2 = d[mt][nt][2] + b0, x3 = d[mt][nt][3] + b1;
            if (SILU) {
                x0 = x0 / (1.f + __expf(-x0));
                x1 = x1 / (1.f + __expf(-x1));
                x2 = x2 / (1.f + __expf(-x2));
                x3 = x3 / (1.f + __expf(-x3));
            }
            if (OSPLIT) {
                __nv_bfloat16 h0, h1, h2, h3, l0, l1, l2, l3;
                split_bf16(x0, h0, l0); split_bf16(x1, h1, l1);
                split_bf16(x2, h2, l2); split_bf16(x3, h3, l3);
                *(__nv_bfloat162*)&Chi[(size_t)row0 * N + col]       = __nv_bfloat162(h0, h1);
                *(__nv_bfloat162*)&Clo[(size_t)row0 * N + col]       = __nv_bfloat162(l0, l1);
                *(__nv_bfloat162*)&Chi[(size_t)(row0 + 8) * N + col] = __nv_bfloat162(h2, h3);
                *(__nv_bfloat162*)&Clo[(size_t)(row0 + 8) * N + col] = __nv_bfloat162(l2, l3);
            } else {
                *(float2*)&C[(size_t)row0 * N + col]       = make_float2(x0, x1);
                *(float2*)&C[(size_t)(row0 + 8) * N + col] = make_float2(x2, x3);
            }
        }
    }
}

// ---------------- fused 2-layer MLP (32-row CTA, high occupancy) ------------
// C = (silu(A@W1+b1)) @ W2 + b2. A pre-split [m][K1]; W1 [128][K1]; W2 [N2][128].
// CTA = 32 rows, 256 thr (8 warps as 2m(16) x 4n(32)). X1 in smem bf16 hi/lo.
// smem (bf16 elems): X1h@0 (32*136) X1l@4352 Ah@8704 (32*72) Al@11008
//   Bh@13312 (128*72) Bl@22528. Total 31744 elems = 63488 B.
#define XGP 136
#define MLP_SMEM (31744 * 2)

__global__ __launch_bounds__(256)
void mlp2_kernel(const __nv_bfloat16* __restrict__ Ahi_g,
                 const __nv_bfloat16* __restrict__ Alo_g,
                 const __nv_bfloat16* __restrict__ W1hi,
                 const __nv_bfloat16* __restrict__ W1lo,
                 const float* __restrict__ b1,
                 const __nv_bfloat16* __restrict__ W2hi,
                 const __nv_bfloat16* __restrict__ W2lo,
                 const float* __restrict__ b2,
                 float* __restrict__ C,
                 int K1, int N2) {
    extern __shared__ __nv_bfloat16 sm[];
    __nv_bfloat16* X1h = sm;
    __nv_bfloat16* X1l = sm + 4352;
    __nv_bfloat16* Ah  = sm + 8704;
    __nv_bfloat16* Al  = sm + 11008;
    __nv_bfloat16* Bh  = sm + 13312;
    __nv_bfloat16* Bl  = sm + 22528;

    int tid = threadIdx.x, wid = tid >> 5, lane = tid & 31;
    int bm = blockIdx.x << 5;        // 32 rows
    int wm = (wid & 1) << 4;         // 2 m-warps of 16
    int wn = (wid >> 1) << 5;        // 4 n-warps over 128
    int g = lane >> 2, tg = lane & 3;
    int a_row = (lane & 15), a_kh = (lane >> 4) << 3;
    int b_row = (lane & 7) + ((lane >> 4) << 3), b_kh = ((lane >> 3) & 1) << 3;

    // ---------------- stage 1: X1 = silu(A @ W1 + b1), 32 x 128 -------------
    float d[4][4];
#pragma unroll
    for (int nt = 0; nt < 4; nt++)
#pragma unroll
        for (int q = 0; q < 4; q++) d[nt][q] = 0.f;

    for (int kc = 0; kc < K1; kc += 64) {
        // stage A 32x64 hi/lo: 256 uint4 per split -> 1 per thread
        {
            int r = tid >> 3, c = (tid & 7) << 3;
            *(uint4*)&Ah[r * GPAD + c] = *(const uint4*)&Ahi_g[(size_t)(bm + r) * K1 + kc + c];
            *(uint4*)&Al[r * GPAD + c] = *(const uint4*)&Alo_g[(size_t)(bm + r) * K1 + kc + c];
        }
        // stage W1 128x64 hi/lo: 1024 uint4 per split -> 4 per thread
#pragma unroll
        for (int it = 0; it < 4; it++) {
            int idx = it * 256 + tid;
            int r = idx >> 3, c = (idx & 7) << 3;
            *(uint4*)&Bh[r * GPAD + c] = *(const uint4*)&W1hi[(size_t)r * K1 + kc + c];
            *(uint4*)&Bl[r * GPAD + c] = *(const uint4*)&W1lo[(size_t)r * K1 + kc + c];
        }
        __syncthreads();
#pragma unroll
        for (int ks = 0; ks < 4; ks++) {
            int k0 = ks * 16;
            uint32_t ah[4], al[4], bh[2][4], bl[2][4];
            ldsm4(ah, &Ah[(wm + a_row) * GPAD + k0 + a_kh]);
            ldsm4(al, &Al[(wm + a_row) * GPAD + k0 + a_kh]);
#pragma unroll
            for (int j = 0; j < 2; j++) {
                ldsm4(bh[j], &Bh[(wn + j * 16 + b_row) * GPAD + k0 + b_kh]);
                ldsm4(bl[j], &Bl[(wn + j * 16 + b_row) * GPAD + k0 + b_kh]);
            }
#pragma unroll
            for (int nt = 0; nt < 4; nt++) {
                const uint32_t* bhp = &bh[nt >> 1][(nt & 1) << 1];
                const uint32_t* blp = &bl[nt >> 1][(nt & 1) << 1];
                mma16816(d[nt], ah, bhp);
                mma16816(d[nt], ah, blp);
                mma16816(d[nt], al, bhp);
            }
        }
        __syncthreads();
    }

    // bias + silu + split -> X1 smem (bf16 hi/lo)
    {
        int r0 = wm + g;
#pragma unroll
        for (int nt = 0; nt < 4; nt++) {
            int col = wn + nt * 8 + tg * 2;
            float b0 = b1[col], bb = b1[col + 1];
            float x0 = d[nt][0] + b0, x1 = d[nt][1] + bb;
            float x2 = d[nt][2] + b0, x3 = d[nt][3] + bb;
            x0 = x0 / (1.f + __expf(-x0));
            x1 = x1 / (1.f + __expf(-x1));
            x2 = x2 / (1.f + __expf(-x2));
            x3 = x3 / (1.f + __expf(-x3));
            __nv_bfloat16 h0, h1, h2, h3, l0, l1, l2, l3;
            split_bf16(x0, h0, l0); split_bf16(x1, h1, l1);
            split_bf16(x2, h2, l2); split_bf16(x3, h3, l3);
            *(__nv_bfloat162*)&X1h[r0 * XGP + col]       = __nv_bfloat162(h0, h1);
            *(__nv_bfloat162*)&X1l[r0 * XGP + col]       = __nv_bfloat162(l0, l1);
            *(__nv_bfloat162*)&X1h[(r0 + 8) * XGP + col] = __nv_bfloat162(h2, h3);
            *(__nv_bfloat162*)&X1l[(r0 + 8) * XGP + col] = __nv_bfloat162(l2, l3);
        }
    }
    __syncthreads();

    // ---------------- stage 2: C = X1 @ W2 + b2, 32 x N2 --------------------
    for (int nc = 0; nc < N2; nc += 128) {
        float e[4][4];
#pragma unroll
        for (int nt = 0; nt < 4; nt++)
#pragma unroll
            for (int q = 0; q < 4; q++) e[nt][q] = 0.f;

        for (int kc2 = 0; kc2 < 2; kc2++) {
            __syncthreads();   // protect B bufs from prior readers
#pragma unroll
            for (int it = 0; it < 4; it++) {
                int idx = it * 256 + tid;
                int r = idx >> 3, c = (idx & 7) << 3;
                *(uint4*)&Bh[r * GPAD + c] = *(const uint4*)&W2hi[(size_t)(nc + r) * 128 + kc2 * 64 + c];
                *(uint4*)&Bl[r * GPAD + c] = *(const uint4*)&W2lo[(size_t)(nc + r) * 128 + kc2 * 64 + c];
            }
            __syncthreads();
#pragma unroll
            for (int ks = 0; ks < 4; ks++) {
                int k0 = ks * 16;
                int ka = kc2 * 64 + k0;
                uint32_t ah[4], al[4], bh[2][4], bl[2][4];
                ldsm4(ah, &X1h[(wm + a_row) * XGP + ka + a_kh]);
                ldsm4(al, &X1l[(wm + a_row) * XGP + ka + a_kh]);
#pragma unroll
                for (int j = 0; j < 2; j++) {
                    ldsm4(bh[j], &Bh[(wn + j * 16 + b_row) * GPAD + k0 + b_kh]);
                    ldsm4(bl[j], &Bl[(wn + j * 16 + b_row) * GPAD + k0 + b_kh]);
                }
#pragma unroll
                for (int nt = 0; nt < 4; nt++) {
                    const uint32_t* bhp = &bh[nt >> 1][(nt & 1) << 1];
                    const uint32_t* blp = &bl[nt >> 1][(nt & 1) << 1];
                    mma16816(e[nt], ah, bhp);
                    mma16816(e[nt], ah, blp);
                    mma16816(e[nt], al, bhp);
                }
            }
        }
        // epilogue for this n-chunk (fp32 out, no activation)
        {
            int row0 = bm + wm + g;
#pragma unroll
            for (int nt = 0; nt < 4; nt++) {
                int col = nc + wn + nt * 8 + tg * 2;
                float b0 = b2[col], bb = b2[col + 1];
                *(float2*)&C[(size_t)row0 * N2 + col] =
                    make_float2(e[nt][0] + b0, e[nt][1] + bb);
                *(float2*)&C[(size_t)(row0 + 8) * N2 + col] =
                    make_float2(e[nt][2] + b0, e[nt][3] + bb);
            }
        }
    }
}

// ---------------- message pass (CSR gather, f32x2 feature pairs) ------------
#define APB 4
#define CH  32
template <bool FIRST>
__global__ __launch_bounds__(64)
void msg_kernel(const float* __restrict__ phi, const float* __restrict__ vin,
                float* __restrict__ s, float* __restrict__ vout,
                __nv_bfloat16* __restrict__ vbh, __nv_bfloat16* __restrict__ vbl,
                const float* __restrict__ rbfW, const float* __restrict__ rbfB,
                const float* __restrict__ egeo, const int* __restrict__ esrc,
                const int* __restrict__ rowstart) {
    int t = threadIdx.x;                  // owns feature pair (2t, 2t+1)
    int f2 = t * 2;
    float2 w1[RR], w2[RR], w3[RR];
#pragma unroll
    for (int r = 0; r < RR; r++) {
        w1[r] = *(const float2*)&rbfW[r * 384 + f2];
        if (!FIRST) w2[r] = *(const float2*)&rbfW[r * 384 + 128 + f2];
        w3[r] = *(const float2*)&rbfW[r * 384 + 256 + f2];
    }
    float2 b1 = *(const float2*)&rbfB[f2];
    float2 b2 = FIRST ? make_float2(0.f, 0.f) : *(const float2*)&rbfB[128 + f2];
    float2 b3 = *(const float2*)&rbfB[256 + f2];

    __shared__ float2 sG[CH][24];   // per-edge scalars duplicated {v,v}
    __shared__ int    sS[CH];

    int a0 = blockIdx.x * APB;
    for (int a = a0; a < a0 + APB; a++) {
        int beg = rowstart[a], end = rowstart[a + 1];
        float2 ds  = make_float2(0.f, 0.f);
        float2 dv0 = ds, dv1 = ds, dv2 = ds;
        for (int c0 = beg; c0 < end; c0 += CH) {
            int nc = min(CH, end - c0);
            __syncthreads();
            for (int i = t; i < nc * 24; i += 64) {
                float v = egeo[(size_t)c0 * 24 + i];
                sG[i / 24][i % 24] = make_float2(v, v);
            }
            if (t < nc) sS[t] = esrc[c0 + t];
            __syncthreads();
            for (int k = 0; k < nc; k++) {
                const float2* gk = sG[k];
                int src = sS[k];
                const float* pb = phi + (size_t)src * 384;
                float2 p0 = *(const float2*)(pb + f2);
                float2 p1, p2;
                p2 = *(const float2*)(pb + 256 + f2);
                float2 v0, v1, v2;
                if (!FIRST) {
                    p1 = *(const float2*)(pb + 128 + f2);
                    const float* vb = vin + (size_t)src * 384;
                    v0 = *(const float2*)(vb + f2);
                    v1 = *(const float2*)(vb + 128 + f2);
                    v2 = *(const float2*)(vb + 256 + f2);
                }
                float2 fc = gk[20];
                float2 wf1 = fmul2(fc, b1);
                float2 wf2 = FIRST ? make_float2(0.f, 0.f) : fmul2(fc, b2);
                float2 wf3 = fmul2(fc, b3);
#pragma unroll
                for (int r = 0; r < RR; r++) {
                    float2 rb = gk[r];
                    wf1 = ffma2(rb, w1[r], wf1);
                    if (!FIRST) wf2 = ffma2(rb, w2[r], wf2);
                    wf3 = ffma2(rb, w3[r], wf3);
                }
                ds = ffma2(p0, wf1, ds);
                float2 dvs = fmul2(p2, wf3);
                dv0 = ffma2(gk[21], dvs, dv0);
                dv1 = ffma2(gk[22], dvs, dv1);
                dv2 = ffma2(gk[23], dvs, dv2);
                if (!FIRST) {
                    float2 dvv = fmul2(p1, wf2);
                    dv0 = ffma2(v0, dvv, dv0);
                    dv1 = ffma2(v1, dvv, dv1);
                    dv2 = ffma2(v2, dvv, dv2);
                }
            }
        }
        size_t sa = (size_t)a * 128 + f2;
        size_t va = (size_t)a * 384 + f2;
        *(float2*)&s[sa] = fadd2(*(const float2*)&s[sa], ds);
        float2 o0, o1, o2;
        if (FIRST) {
            o0 = dv0; o1 = dv1; o2 = dv2;
        } else {
            o0 = fadd2(*(const float2*)&vin[va],       dv0);
            o1 = fadd2(*(const float2*)&vin[va + 128], dv1);
            o2 = fadd2(*(const float2*)&vin[va + 256], dv2);
        }
        *(float2*)&vout[va]       = o0;
        *(float2*)&vout[va + 128] = o1;
        *(float2*)&vout[va + 256] = o2;
        __nv_bfloat16 h0, h1, l0, l1;
        split_bf16(o0.x, h0, l0); split_bf16(o0.y, h1, l1);
        *(__nv_bfloat162*)&vbh[va]       = __nv_bfloat162(h0, h1);
        *(__nv_bfloat162*)&vbl[va]       = __nv_bfloat162(l0, l1);
        split_bf16(o1.x, h0, l0); split_bf16(o1.y, h1, l1);
        *(__nv_bfloat162*)&vbh[va + 128] = __nv_bfloat162(h0, h1);
        *(__nv_bfloat162*)&vbl[va + 128] = __nv_bfloat162(l0, l1);
        split_bf16(o2.x, h0, l0); split_bf16(o2.y, h1, l1);
        *(__nv_bfloat162*)&vbh[va + 256] = __nv_bfloat162(h0, h1);
        *(__nv_bfloat162*)&vbl[va + 256] = __nv_bfloat162(l0, l1);
    }
}

// ---------------- per-atom update pieces ------------------------------------
// uvv layout: [atom*3 + c][256] with cols 0..127 = uv, 128..255 = vv
__global__ void cat_kernel(const float* __restrict__ s, const float* __restrict__ uvv,
                           __nv_bfloat16* __restrict__ cth,
                           __nv_bfloat16* __restrict__ ctl) {
    int i = blockIdx.x * blockDim.x + threadIdx.x;
    if (i >= NA * FF) return;
    int atom = i >> 7, f = i & 127;
    size_t base = (size_t)atom * 3 * 256 + 128 + f;
    float x0 = uvv[base], x1 = uvv[base + 256], x2 = uvv[base + 512];
    float n = sqrtf(x0 * x0 + x1 * x1 + x2 * x2 + 1e-8f);
    __nv_bfloat16 h, l;
    size_t c0 = (size_t)atom * 256 + f;
    split_bf16(s[i], h, l);
    cth[c0] = h; ctl[c0] = l;
    split_bf16(n, h, l);
    cth[c0 + 128] = h; ctl[c0 + 128] = l;
}

__global__ void upd_kernel(const float* __restrict__ uvv,
                           const float* __restrict__ a,
                           float* __restrict__ s,
                           __nv_bfloat16* __restrict__ sh, __nv_bfloat16* __restrict__ sl,
                           const float* __restrict__ vB, float* __restrict__ vA) {
    int i = blockIdx.x * blockDim.x + threadIdx.x;
    if (i >= NA * FF) return;
    int atom = i >> 7, f = i & 127;
    size_t ub = (size_t)atom * 3 * 256 + f;
    float u0 = uvv[ub],       u1 = uvv[ub + 256], u2 = uvv[ub + 512];
    float x0 = uvv[ub + 128], x1 = uvv[ub + 384], x2 = uvv[ub + 640];
    float dot = u0 * x0 + u1 * x1 + u2 * x2;
    size_t off = (size_t)atom * 384;
    float a_vv = a[off + f], a_sv = a[off + 128 + f], a_ss = a[off + 256 + f];
    float sn = s[i] + a_ss + a_sv * dot;
    s[i] = sn;
    __nv_bfloat16 h, l;
    split_bf16(sn, h, l);
    sh[i] = h; sl[i] = l;
    vA[off + f]       = vB[off + f]       + a_vv * u0;
    vA[off + 128 + f] = vB[off + 128 + f] + a_vv * u1;
    vA[off + 256 + f] = vB[off + 256 + f] + a_vv * u2;
}

// ---------------- readout: GEMV + molecule segment sum ---------------------
__global__ void out2_kernel(const float* __restrict__ h, const float* __restrict__ w2,
                            const float* __restrict__ b2, const int* __restrict__ mol,
                            float* __restrict__ out) {
    int gw = (blockIdx.x * blockDim.x + threadIdx.x) >> 5;
    int lane = threadIdx.x & 31;
    if (gw >= NA) return;
    const float* hp = h + (size_t)gw * FF;
    float sum = 0.f;
#pragma unroll
    for (int i = lane; i < FF; i += 32) sum = fmaf(hp[i], w2[i], sum);
#pragma unroll
    for (int o = 16; o; o >>= 1) sum += __shfl_down_sync(0xffffffffu, sum, o);
    if (lane == 0) atomicAdd(&out[mol[gw]], sum + b2[0]);
}

// ---------------- host-side launch ------------------------------------------
static float* symf(const void* sym) {
    void* p = nullptr;
    cudaGetSymbolAddress(&p, sym);
    return (float*)p;
}
static int* symi(const void* sym) {
    void* p = nullptr;
    cudaGetSymbolAddress(&p, sym);
    return (int*)p;
}
static __nv_bfloat16* symb(const void* sym) {
    void* p = nullptr;
    cudaGetSymbolAddress(&p, sym);
    return (__nv_bfloat16*)p;
}

extern "C" void kernel_launch(void* const* d_in, const int* in_sizes, int n_in,
                              void* d_out, int out_size) {
    const int*   z        = (const int*)  d_in[0];
    const float* pos      = (const float*)d_in[1];
    const int*   edge_src = (const int*)  d_in[2];
    const int*   edge_dst = (const int*)  d_in[3];
    const int*   mol_idx  = (const int*)  d_in[4];
    const float* embed    = (const float*)d_in[5];
    const float* msg_w1   = (const float*)d_in[6];
    const float* msg_b1   = (const float*)d_in[7];
    const float* msg_w2   = (const float*)d_in[8];
    const float* msg_b2   = (const float*)d_in[9];
    const float* rbf_w    = (const float*)d_in[10];
    const float* rbf_b    = (const float*)d_in[11];
    const float* upd_u    = (const float*)d_in[12];
    const float* upd_v    = (const float*)d_in[13];
    const float* upd_a1   = (const float*)d_in[14];
    const float* upd_a1b  = (const float*)d_in[15];
    const float* upd_a2   = (const float*)d_in[16];
    const float* upd_a2b  = (const float*)d_in[17];
    const float* out_w1   = (const float*)d_in[18];
    const float* out_b1   = (const float*)d_in[19];
    const float* out_w2   = (const float*)d_in[20];
    const float* out_b2   = (const float*)d_in[21];
    float* out = (float*)d_out;

    float* s    = symf(g_s);
    float* vA   = symf(g_vA);
    float* vB   = symf(g_vB);
    float* h    = symf(g_h);
    float* phi  = symf(g_phi);
    float* uvv  = symf(g_uvv);
    float* a    = symf(g_a);
    float* egeo = symf(g_egeo);
    int* esrc   = symi(g_esrc);
    int* rowst  = symi(g_rowstart);
    int* cursor = symi(g_cursor);
    int* count  = symi(g_count);
    __nv_bfloat16* whi = symb(g_whi);
    __nv_bfloat16* wlo = symb(g_wlo);
    __nv_bfloat16* sh  = symb(g_sh),  *sl  = symb(g_sl);
    __nv_bfloat16* vbh = symb(g_vbh), *vbl = symb(g_vbl);
    __nv_bfloat16* cth = symb(g_cth), *ctl = symb(g_ctl);

    cudaFuncSetAttribute(gemm_mma<true,  false>, cudaFuncAttributeMaxDynamicSharedMemorySize, GT_SMEM);
    cudaFuncSetAttribute(gemm_mma<false, false>, cudaFuncAttributeMaxDynamicSharedMemorySize, GT_SMEM);
    cudaFuncSetAttribute(mlp2_kernel, cudaFuncAttributeMaxDynamicSharedMemorySize, MLP_SMEM);

    // prelude ordered so launch index 3 = first mlp2 (profiled slot)
    embed_kernel<<<(NA * 32 + 255) / 256, 256>>>(z, embed, s, sh, sl);
    wprep_all<<<(557056 + 255) / 256, 256>>>(msg_w1, msg_w2, upd_u, upd_v,
                                             upd_a1, upd_a2, out_w1, whi, wlo,
                                             count, out);
    count_kernel<<<(NE + 255) / 256, 256>>>(edge_dst, count);

    bool csr_done = false;
    for (int l = 0; l < LL; l++) {
        size_t LB = (size_t)l * 180224;
        const float* bb1 = msg_b1  + (size_t)l * FF;
        const float* bb2 = msg_b2  + (size_t)l * 3 * FF;
        const float* rw  = rbf_w   + (size_t)l * RR * 3 * FF;
        const float* rb  = rbf_b   + (size_t)l * 3 * FF;
        const float* a1b = upd_a1b + (size_t)l * FF;
        const float* a2b = upd_a2b + (size_t)l * 3 * FF;

        // fused s -> h -> phi  (launch index 3 on first iteration)
        mlp2_kernel<<<NA / 32, 256, MLP_SMEM>>>(sh, sl,
            whi + LB, wlo + LB, bb1,
            whi + LB + 16384, wlo + LB + 16384, bb2,
            phi, 128, 384);
        if (!csr_done) {
            scan_kernel<<<1, 1024>>>(count, rowst, cursor);
            fill_kernel<<<(NE + 255) / 256, 256>>>(edge_src, edge_dst, pos, cursor, egeo, esrc);
            csr_done = true;
        }
        if (l == 0)
            msg_kernel<true ><<<NA / APB, 64>>>(phi, vA, s, vB, vbh, vbl, rw, rb, egeo, esrc, rowst);
        else
            msg_kernel<false><<<NA / APB, 64>>>(phi, vA, s, vB, vbh, vbl, rw, rb, egeo, esrc, rowst);
        gemm_mma<false, false><<<dim3(4, 384), 128, GT_SMEM>>>(vbh, vbl,
            whi + LB + 65536, wlo + LB + 65536, nullptr, uvv, nullptr, nullptr, NA * 3, 256, 128);
        cat_kernel<<<(NA * FF + 255) / 256, 256>>>(s, uvv, cth, ctl);
        // fused cat -> ah -> a
        mlp2_kernel<<<NA / 32, 256, MLP_SMEM>>>(cth, ctl,
            whi + LB + 98304, wlo + LB + 98304, a1b,
            whi + LB + 131072, wlo + LB + 131072, a2b,
            a, 256, 384);
        upd_kernel<<<(NA * FF + 255) / 256, 256>>>(uvv, a, s, sh, sl, vB, vA);
    }

    gemm_mma<true, false><<<dim3(2, 128), 128, GT_SMEM>>>(sh, sl,
        whi + 540672, wlo + 540672, out_b1, h, nullptr, nullptr, NA, 128, 128);
    out2_kernel<<<NA * 32 / 256, 256>>>(h, out_w2, out_b2, mol_idx, out);
}

// round 10
// speedup vs baseline: 1.0241x; 1.0087x over previous
#include <cuda_runtime.h>
#include <cuda_bf16.h>
#include <math.h>
#include <stdint.h>

#define NA   8192
#define NE   262144
#define NMOL 128
#define FF   128
#define RR   20
#define LL   3
#define PI_F 3.14159265358979f

// ---------------- scratch (device globals; no runtime alloc allowed) -------
__device__ float g_s  [NA * FF];
__device__ float g_vA [NA * 3 * FF];
__device__ float g_vB [NA * 3 * FF];
__device__ float g_h  [NA * FF];
__device__ float g_phi[NA * 3 * FF];
__device__ float g_uvv[NA * 3 * 2 * FF];      // fused [atom*3][256]: uv | vv
__device__ float g_a  [NA * 3 * FF];
__device__ float g_egeo[NE * 24];             // per sorted edge: rbf*fc[20], fc, unit[3]
__device__ int   g_esrc[NE];
__device__ int   g_rowstart[NA + 1];
__device__ int   g_cursor[NA];
__device__ int   g_count[NA];
// bf16 hi/lo weight blobs, N-major [n][k]
#define WBLOB_ELEMS (34 * 16384)
__device__ __nv_bfloat16 g_whi[WBLOB_ELEMS];
__device__ __nv_bfloat16 g_wlo[WBLOB_ELEMS];
// bf16 hi/lo activation (A-operand) arrays, k-major rows
__device__ __nv_bfloat16 g_sh [NA * FF],     g_sl [NA * FF];
__device__ __nv_bfloat16 g_vbh[NA * 3 * FF], g_vbl[NA * 3 * FF];
__device__ __nv_bfloat16 g_cth[NA * 2 * FF], g_ctl[NA * 2 * FF];

// ---------------- packed f32x2 helpers --------------------------------------
__device__ __forceinline__ float2 ffma2(float2 a, float2 b, float2 c) {
    float2 d;
    asm("fma.rn.f32x2 %0, %1, %2, %3;"
        : "=l"(*reinterpret_cast<unsigned long long*>(&d))
        : "l"(*reinterpret_cast<unsigned long long*>(&a)),
          "l"(*reinterpret_cast<unsigned long long*>(&b)),
          "l"(*reinterpret_cast<unsigned long long*>(&c)));
    return d;
}
__device__ __forceinline__ float2 fmul2(float2 a, float2 b) {
    float2 d;
    asm("mul.rn.f32x2 %0, %1, %2;"
        : "=l"(*reinterpret_cast<unsigned long long*>(&d))
        : "l"(*reinterpret_cast<unsigned long long*>(&a)),
          "l"(*reinterpret_cast<unsigned long long*>(&b)));
    return d;
}
__device__ __forceinline__ float2 fadd2(float2 a, float2 b) {
    float2 d;
    asm("add.rn.f32x2 %0, %1, %2;"
        : "=l"(*reinterpret_cast<unsigned long long*>(&d))
        : "l"(*reinterpret_cast<unsigned long long*>(&a)),
          "l"(*reinterpret_cast<unsigned long long*>(&b)));
    return d;
}
__device__ __forceinline__ void split_bf16(float x, __nv_bfloat16& h, __nv_bfloat16& l) {
    h = __float2bfloat16(x);
    l = __float2bfloat16(x - __bfloat162float(h));
}

// ---------------- init / small kernels --------------------------------------
__global__ void embed_kernel(const int* __restrict__ z,
                             const float* __restrict__ embed,
                             float* __restrict__ s,
                             __nv_bfloat16* __restrict__ sh,
                             __nv_bfloat16* __restrict__ sl) {
    int i = blockIdx.x * blockDim.x + threadIdx.x;
    if (i >= NA * 32) return;
    int atom = i >> 5, q = i & 31;
    float4 v = ((const float4*)(embed + (size_t)z[atom] * FF))[q];
    ((float4*)s)[i] = v;
    __nv_bfloat16 h0, h1, h2, h3, l0, l1, l2, l3;
    split_bf16(v.x, h0, l0); split_bf16(v.y, h1, l1);
    split_bf16(v.z, h2, l2); split_bf16(v.w, h3, l3);
    uint2 hp, lp;
    hp.x = ((uint32_t)__bfloat16_as_ushort(h1) << 16) | __bfloat16_as_ushort(h0);
    hp.y = ((uint32_t)__bfloat16_as_ushort(h3) << 16) | __bfloat16_as_ushort(h2);
    lp.x = ((uint32_t)__bfloat16_as_ushort(l1) << 16) | __bfloat16_as_ushort(l0);
    lp.y = ((uint32_t)__bfloat16_as_ushort(l3) << 16) | __bfloat16_as_ushort(l2);
    ((uint2*)sh)[i] = hp;
    ((uint2*)sl)[i] = lp;
}

// one-shot weight prep (+ init of count/out): fp32 W[K][N] -> bf16 hi/lo [n][K].
// Per-layer blob (elements): w1@0 w2@16384 u@65536 v@81920 a1@98304 a2@131072
// out_w1 @ 540672. Total 557056.
__global__ void wprep_all(const float* __restrict__ msg_w1,
                          const float* __restrict__ msg_w2,
                          const float* __restrict__ upd_u,
                          const float* __restrict__ upd_v,
                          const float* __restrict__ upd_a1,
                          const float* __restrict__ upd_a2,
                          const float* __restrict__ out_w1,
                          __nv_bfloat16* __restrict__ hi,
                          __nv_bfloat16* __restrict__ lo,
                          int* __restrict__ cnt, float* __restrict__ outp) {
    int i = blockIdx.x * blockDim.x + threadIdx.x;
    if (i < NA) cnt[i] = 0;
    if (i < NMOL) outp[i] = 0.f;
    if (i >= 557056) return;
    const float* src;
    int K, N, idx, segbase;
    if (i >= 540672) {
        src = out_w1; K = 128; N = 128; idx = i - 540672; segbase = 540672;
    } else {
        int l = i / 180224;
        int r = i - l * 180224;
        if (r < 16384)       { src = msg_w1 + l * 16384; K = 128; N = 128; idx = r;          segbase = l * 180224; }
        else if (r < 65536)  { src = msg_w2 + l * 49152; K = 128; N = 384; idx = r - 16384;  segbase = l * 180224 + 16384; }
        else if (r < 81920)  { src = upd_u  + l * 16384; K = 128; N = 128; idx = r - 65536;  segbase = l * 180224 + 65536; }
        else if (r < 98304)  { src = upd_v  + l * 16384; K = 128; N = 128; idx = r - 81920;  segbase = l * 180224 + 81920; }
        else if (r < 131072) { src = upd_a1 + l * 32768; K = 256; N = 128; idx = r - 98304;  segbase = l * 180224 + 98304; }
        else                 { src = upd_a2 + l * 49152; K = 128; N = 384; idx = r - 131072; segbase = l * 180224 + 131072; }
    }
    int k = idx / N, n = idx - k * N;
    float a = src[idx];
    __nv_bfloat16 h, l2;
    split_bf16(a, h, l2);
    hi[(size_t)segbase + (size_t)n * K + k] = h;
    lo[(size_t)segbase + (size_t)n * K + k] = l2;
}

// ---------------- CSR build + edge geometry --------------------------------
__global__ void count_kernel(const int* __restrict__ dst, int* __restrict__ cnt) {
    int e = blockIdx.x * blockDim.x + threadIdx.x;
    if (e < NE) atomicAdd(&cnt[dst[e]], 1);
}

__global__ void scan_kernel(const int* __restrict__ cnt,
                            int* __restrict__ rowstart,
                            int* __restrict__ cursor) {
    __shared__ int part[1024];
    int t = threadIdx.x;
    int loc[8], ex[8];
    int run = 0;
#pragma unroll
    for (int i = 0; i < 8; i++) {
        loc[i] = cnt[t * 8 + i];
        ex[i]  = run;
        run   += loc[i];
    }
    part[t] = run;
    __syncthreads();
    for (int off = 1; off < 1024; off <<= 1) {
        int v = (t >= off) ? part[t - off] : 0;
        __syncthreads();
        part[t] += v;
        __syncthreads();
    }
    int base = (t > 0) ? part[t - 1] : 0;
#pragma unroll
    for (int i = 0; i < 8; i++) {
        int rs = base + ex[i];
        rowstart[t * 8 + i] = rs;
        cursor[t * 8 + i]   = rs;
    }
    if (t == 1023) rowstart[NA] = part[1023];
}

__global__ void fill_kernel(const int* __restrict__ src,
                            const int* __restrict__ dst,
                            const float* __restrict__ pos,
                            int* __restrict__ cursor,
                            float* __restrict__ egeo,
                            int* __restrict__ esrc) {
    int e = blockIdx.x * blockDim.x + threadIdx.x;
    if (e >= NE) return;
    int sd = src[e], dd = dst[e];
    int p = atomicAdd(&cursor[dd], 1);
    float dx = pos[dd * 3 + 0] - pos[sd * 3 + 0];
    float dy = pos[dd * 3 + 1] - pos[sd * 3 + 1];
    float dz = pos[dd * 3 + 2] - pos[sd * 3 + 2];
    float d  = sqrtf(dx * dx + dy * dy + dz * dz + 1e-8f);
    float inv = 1.f / d;
    float fc = 0.5f * (cosf(PI_F * d / 5.0f) + 1.0f) * (d < 5.0f ? 1.f : 0.f);
    float* g = egeo + (size_t)p * 24;
#pragma unroll
    for (int r = 0; r < RR; r++) {
        float freq = (float)(r + 1) * (PI_F / 5.0f);
        g[r] = sinf(d * freq) * inv * fc;
    }
    g[20] = fc;
    g[21] = dx * inv; g[22] = dy * inv; g[23] = dz * inv;
    esrc[p] = sd;
}

// ---------------- MMA primitives --------------------------------------------
__device__ __forceinline__ void mma16816(float* d, const uint32_t* a, const uint32_t* b) {
    asm volatile(
        "mma.sync.aligned.m16n8k16.row.col.f32.bf16.bf16.f32 "
        "{%0,%1,%2,%3}, {%4,%5,%6,%7}, {%8,%9}, {%0,%1,%2,%3};"
        : "+f"(d[0]), "+f"(d[1]), "+f"(d[2]), "+f"(d[3])
        : "r"(a[0]), "r"(a[1]), "r"(a[2]), "r"(a[3]), "r"(b[0]), "r"(b[1]));
}
__device__ __forceinline__ void ldsm4(uint32_t* r, const __nv_bfloat16* p) {
    uint32_t addr = (uint32_t)__cvta_generic_to_shared(p);
    asm volatile("ldmatrix.sync.aligned.m8n8.x4.shared.b16 {%0,%1,%2,%3}, [%4];"
        : "=r"(r[0]), "=r"(r[1]), "=r"(r[2]), "=r"(r[3]) : "r"(addr));
}

// ---------------- standalone HMMA GEMM (64x64 CTA tile) ---------------------
#define GPAD 72
#define GT_SMEM (4 * 64 * GPAD * 2)

template <bool SILU, bool OSPLIT>
__global__ __launch_bounds__(128)
void gemm_mma(const __nv_bfloat16* __restrict__ Ahi_g,
              const __nv_bfloat16* __restrict__ Alo_g,
              const __nv_bfloat16* __restrict__ Whi,
              const __nv_bfloat16* __restrict__ Wlo,
              const float* __restrict__ bias, float* __restrict__ C,
              __nv_bfloat16* __restrict__ Chi, __nv_bfloat16* __restrict__ Clo,
              int M, int N, int K) {
    extern __shared__ __nv_bfloat16 sm[];
    __nv_bfloat16* Ahi = sm;
    __nv_bfloat16* Alo = sm + 64 * GPAD;
    __nv_bfloat16* Bhi = sm + 2 * 64 * GPAD;
    __nv_bfloat16* Blo = sm + 3 * 64 * GPAD;

    int tid = threadIdx.x, wid = tid >> 5, lane = tid & 31;
    int bm = blockIdx.y << 6, bn = blockIdx.x << 6;
    int wm = (wid & 1) << 5, wn = (wid >> 1) << 5;
    int g = lane >> 2, tg = lane & 3;

    float d[2][4][4];
#pragma unroll
    for (int mt = 0; mt < 2; mt++)
#pragma unroll
        for (int nt = 0; nt < 4; nt++)
#pragma unroll
            for (int q = 0; q < 4; q++) d[mt][nt][q] = 0.f;

    int a_row = (lane & 15), a_kh = (lane >> 4) << 3;
    int b_row = (lane & 7) + ((lane >> 4) << 3), b_kh = ((lane >> 3) & 1) << 3;

    for (int kc = 0; kc < K; kc += 64) {
#pragma unroll
        for (int it = 0; it < 4; it++) {
            int idx = it * 128 + tid;
            int r = idx >> 3, c = (idx & 7) << 3;
            *(uint4*)&Ahi[r * GPAD + c] = *(const uint4*)&Ahi_g[(size_t)(bm + r) * K + kc + c];
            *(uint4*)&Alo[r * GPAD + c] = *(const uint4*)&Alo_g[(size_t)(bm + r) * K + kc + c];
            *(uint4*)&Bhi[r * GPAD + c] = *(const uint4*)&Whi[(size_t)(bn + r) * K + kc + c];
            *(uint4*)&Blo[r * GPAD + c] = *(const uint4*)&Wlo[(size_t)(bn + r) * K + kc + c];
        }
        __syncthreads();

#pragma unroll
        for (int ks = 0; ks < 4; ks++) {
            int k0 = ks * 16;
            uint32_t ah[2][4], al[2][4], bh[2][4], bl[2][4];
#pragma unroll
            for (int mt = 0; mt < 2; mt++) {
                ldsm4(ah[mt], &Ahi[(wm + mt * 16 + a_row) * GPAD + k0 + a_kh]);
                ldsm4(al[mt], &Alo[(wm + mt * 16 + a_row) * GPAD + k0 + a_kh]);
            }
#pragma unroll
            for (int j = 0; j < 2; j++) {
                ldsm4(bh[j], &Bhi[(wn + j * 16 + b_row) * GPAD + k0 + b_kh]);
                ldsm4(bl[j], &Blo[(wn + j * 16 + b_row) * GPAD + k0 + b_kh]);
            }
#pragma unroll
            for (int mt = 0; mt < 2; mt++)
#pragma unroll
                for (int nt = 0; nt < 4; nt++) {
                    const uint32_t* bhp = &bh[nt >> 1][(nt & 1) << 1];
                    const uint32_t* blp = &bl[nt >> 1][(nt & 1) << 1];
                    mma16816(d[mt][nt], ah[mt], bhp);
                    mma16816(d[mt][nt], ah[mt], blp);
                    mma16816(d[mt][nt], al[mt], bhp);
                }
        }
        __syncthreads();
    }

#pragma unroll
    for (int mt = 0; mt < 2; mt++) {
        int row0 = bm + wm + mt * 16 + g;
#pragma unroll
        for (int nt = 0; nt < 4; nt++) {
            int col = bn + wn + nt * 8 + tg * 2;
            float b0 = 0.f, b1 = 0.f;
            if (bias) { b0 = bias[col]; b1 = bias[col + 1]; }
            float x0 = d[mt][nt][0] + b0, x1 = d[mt][nt][1] + b1;
            float x2 = d[mt][nt][2] + b0, x3 = d[mt][nt][3] + b1;
            if (SILU) {
                x0 = x0 / (1.f + __expf(-x0));
                x1 = x1 / (1.f + __expf(-x1));
                x2 = x2 / (1.f + __expf(-x2));
                x3 = x3 / (1.f + __expf(-x3));
            }
            if (OSPLIT) {
                __nv_bfloat16 h0, h1, h2, h3, l0, l1, l2, l3;
                split_bf16(x0, h0, l0); split_bf16(x1, h1, l1);
                split_bf16(x2, h2, l2); split_bf16(x3, h3, l3);
                *(__nv_bfloat162*)&Chi[(size_t)row0 * N + col]       = __nv_bfloat162(h0, h1);
                *(__nv_bfloat162*)&Clo[(size_t)row0 * N + col]       = __nv_bfloat162(l0, l1);
                *(__nv_bfloat162*)&Chi[(size_t)(row0 + 8) * N + col] = __nv_bfloat162(h2, h3);
                *(__nv_bfloat162*)&Clo[(size_t)(row0 + 8) * N + col] = __nv_bfloat162(l2, l3);
            } else {
                *(float2*)&C[(size_t)row0 * N + col]       = make_float2(x0, x1);
                *(float2*)&C[(size_t)(row0 + 8) * N + col] = make_float2(x2, x3);
            }
        }
    }
}

// ---------------- fused 2-layer MLP (32-row CTA, high occupancy) ------------
// C = (silu(A@W1+b1)) @ W2 + b2. A pre-split [m][K1]; W1 [128][K1]; W2 [N2][128].
// CTA = 32 rows, 256 thr (8 warps as 2m(16) x 4n(32)). X1 in smem bf16 hi/lo.
#define XGP 136
#define MLP_SMEM (31744 * 2)

__global__ __launch_bounds__(256)
void mlp2_kernel(const __nv_bfloat16* __restrict__ Ahi_g,
                 const __nv_bfloat16* __restrict__ Alo_g,
                 const __nv_bfloat16* __restrict__ W1hi,
                 const __nv_bfloat16* __restrict__ W1lo,
                 const float* __restrict__ b1,
                 const __nv_bfloat16* __restrict__ W2hi,
                 const __nv_bfloat16* __restrict__ W2lo,
                 const float* __restrict__ b2,
                 float* __restrict__ C,
                 int K1, int N2) {
    extern __shared__ __nv_bfloat16 sm[];
    __nv_bfloat16* X1h = sm;
    __nv_bfloat16* X1l = sm + 4352;
    __nv_bfloat16* Ah  = sm + 8704;
    __nv_bfloat16* Al  = sm + 11008;
    __nv_bfloat16* Bh  = sm + 13312;
    __nv_bfloat16* Bl  = sm + 22528;

    int tid = threadIdx.x, wid = tid >> 5, lane = tid & 31;
    int bm = blockIdx.x << 5;        // 32 rows
    int wm = (wid & 1) << 4;         // 2 m-warps of 16
    int wn = (wid >> 1) << 5;        // 4 n-warps over 128
    int g = lane >> 2, tg = lane & 3;
    int a_row = (lane & 15), a_kh = (lane >> 4) << 3;
    int b_row = (lane & 7) + ((lane >> 4) << 3), b_kh = ((lane >> 3) & 1) << 3;

    // ---------------- stage 1: X1 = silu(A @ W1 + b1), 32 x 128 -------------
    float d[4][4];
#pragma unroll
    for (int nt = 0; nt < 4; nt++)
#pragma unroll
        for (int q = 0; q < 4; q++) d[nt][q] = 0.f;

    for (int kc = 0; kc < K1; kc += 64) {
        {
            int r = tid >> 3, c = (tid & 7) << 3;
            *(uint4*)&Ah[r * GPAD + c] = *(const uint4*)&Ahi_g[(size_t)(bm + r) * K1 + kc + c];
            *(uint4*)&Al[r * GPAD + c] = *(const uint4*)&Alo_g[(size_t)(bm + r) * K1 + kc + c];
        }
#pragma unroll
        for (int it = 0; it < 4; it++) {
            int idx = it * 256 + tid;
            int r = idx >> 3, c = (idx & 7) << 3;
            *(uint4*)&Bh[r * GPAD + c] = *(const uint4*)&W1hi[(size_t)r * K1 + kc + c];
            *(uint4*)&Bl[r * GPAD + c] = *(const uint4*)&W1lo[(size_t)r * K1 + kc + c];
        }
        __syncthreads();
#pragma unroll
        for (int ks = 0; ks < 4; ks++) {
            int k0 = ks * 16;
            uint32_t ah[4], al[4], bh[2][4], bl[2][4];
            ldsm4(ah, &Ah[(wm + a_row) * GPAD + k0 + a_kh]);
            ldsm4(al, &Al[(wm + a_row) * GPAD + k0 + a_kh]);
#pragma unroll
            for (int j = 0; j < 2; j++) {
                ldsm4(bh[j], &Bh[(wn + j * 16 + b_row) * GPAD + k0 + b_kh]);
                ldsm4(bl[j], &Bl[(wn + j * 16 + b_row) * GPAD + k0 + b_kh]);
            }
#pragma unroll
            for (int nt = 0; nt < 4; nt++) {
                const uint32_t* bhp = &bh[nt >> 1][(nt & 1) << 1];
                const uint32_t* blp = &bl[nt >> 1][(nt & 1) << 1];
                mma16816(d[nt], ah, bhp);
                mma16816(d[nt], ah, blp);
                mma16816(d[nt], al, bhp);
            }
        }
        __syncthreads();
    }

    // bias + silu + split -> X1 smem (bf16 hi/lo)
    {
        int r0 = wm + g;
#pragma unroll
        for (int nt = 0; nt < 4; nt++) {
            int col = wn + nt * 8 + tg * 2;
            float b0 = b1[col], bb = b1[col + 1];
            float x0 = d[nt][0] + b0, x1 = d[nt][1] + bb;
            float x2 = d[nt][2] + b0, x3 = d[nt][3] + bb;
            x0 = x0 / (1.f + __expf(-x0));
            x1 = x1 / (1.f + __expf(-x1));
            x2 = x2 / (1.f + __expf(-x2));
            x3 = x3 / (1.f + __expf(-x3));
            __nv_bfloat16 h0, h1, h2, h3, l0, l1, l2, l3;
            split_bf16(x0, h0, l0); split_bf16(x1, h1, l1);
            split_bf16(x2, h2, l2); split_bf16(x3, h3, l3);
            *(__nv_bfloat162*)&X1h[r0 * XGP + col]       = __nv_bfloat162(h0, h1);
            *(__nv_bfloat162*)&X1l[r0 * XGP + col]       = __nv_bfloat162(l0, l1);
            *(__nv_bfloat162*)&X1h[(r0 + 8) * XGP + col] = __nv_bfloat162(h2, h3);
            *(__nv_bfloat162*)&X1l[(r0 + 8) * XGP + col] = __nv_bfloat162(l2, l3);
        }
    }
    __syncthreads();

    // ---------------- stage 2: C = X1 @ W2 + b2, 32 x N2 --------------------
    for (int nc = 0; nc < N2; nc += 128) {
        float e[4][4];
#pragma unroll
        for (int nt = 0; nt < 4; nt++)
#pragma unroll
            for (int q = 0; q < 4; q++) e[nt][q] = 0.f;

        for (int kc2 = 0; kc2 < 2; kc2++) {
            __syncthreads();
#pragma unroll
            for (int it = 0; it < 4; it++) {
                int idx = it * 256 + tid;
                int r = idx >> 3, c = (idx & 7) << 3;
                *(uint4*)&Bh[r * GPAD + c] = *(const uint4*)&W2hi[(size_t)(nc + r) * 128 + kc2 * 64 + c];
                *(uint4*)&Bl[r * GPAD + c] = *(const uint4*)&W2lo[(size_t)(nc + r) * 128 + kc2 * 64 + c];
            }
            __syncthreads();
#pragma unroll
            for (int ks = 0; ks < 4; ks++) {
                int k0 = ks * 16;
                int ka = kc2 * 64 + k0;
                uint32_t ah[4], al[4], bh[2][4], bl[2][4];
                ldsm4(ah, &X1h[(wm + a_row) * XGP + ka + a_kh]);
                ldsm4(al, &X1l[(wm + a_row) * XGP + ka + a_kh]);
#pragma unroll
                for (int j = 0; j < 2; j++) {
                    ldsm4(bh[j], &Bh[(wn + j * 16 + b_row) * GPAD + k0 + b_kh]);
                    ldsm4(bl[j], &Bl[(wn + j * 16 + b_row) * GPAD + k0 + b_kh]);
                }
#pragma unroll
                for (int nt = 0; nt < 4; nt++) {
                    const uint32_t* bhp = &bh[nt >> 1][(nt & 1) << 1];
                    const uint32_t* blp = &bl[nt >> 1][(nt & 1) << 1];
                    mma16816(e[nt], ah, bhp);
                    mma16816(e[nt], ah, blp);
                    mma16816(e[nt], al, bhp);
                }
            }
        }
        {
            int row0 = bm + wm + g;
#pragma unroll
            for (int nt = 0; nt < 4; nt++) {
                int col = nc + wn + nt * 8 + tg * 2;
                float b0 = b2[col], bb = b2[col + 1];
                *(float2*)&C[(size_t)row0 * N2 + col] =
                    make_float2(e[nt][0] + b0, e[nt][1] + bb);
                *(float2*)&C[(size_t)(row0 + 8) * N2 + col] =
                    make_float2(e[nt][2] + b0, e[nt][3] + bb);
            }
        }
    }
}

// ---------------- message pass (CSR gather, 2 edge-groups x 64 feat-threads)
#define APB 4
#define CH  32
template <bool FIRST>
__global__ __launch_bounds__(128)
void msg_kernel(const float* __restrict__ phi, const float* __restrict__ vin,
                float* __restrict__ s, float* __restrict__ vout,
                __nv_bfloat16* __restrict__ vbh, __nv_bfloat16* __restrict__ vbl,
                const float* __restrict__ rbfW, const float* __restrict__ rbfB,
                const float* __restrict__ egeo, const int* __restrict__ esrc,
                const int* __restrict__ rowstart) {
    int tid = threadIdx.x;
    int t   = tid & 63;                  // feature pair (2t, 2t+1)
    int grp = tid >> 6;                  // edge group 0/1
    int f2 = t * 2;
    float2 w1[RR], w2[RR], w3[RR];
#pragma unroll
    for (int r = 0; r < RR; r++) {
        w1[r] = *(const float2*)&rbfW[r * 384 + f2];
        if (!FIRST) w2[r] = *(const float2*)&rbfW[r * 384 + 128 + f2];
        w3[r] = *(const float2*)&rbfW[r * 384 + 256 + f2];
    }
    float2 b1 = *(const float2*)&rbfB[f2];
    float2 b2 = FIRST ? make_float2(0.f, 0.f) : *(const float2*)&rbfB[128 + f2];
    float2 b3 = *(const float2*)&rbfB[256 + f2];

    __shared__ float2 sG[CH][24];        // per-edge scalars duplicated {v,v}
    __shared__ int    sS[CH];
    __shared__ float2 sP[64][4];         // group-1 partials: ds,dv0,dv1,dv2

    int a0 = blockIdx.x * APB;
    for (int a = a0; a < a0 + APB; a++) {
        int beg = rowstart[a], end = rowstart[a + 1];
        float2 ds  = make_float2(0.f, 0.f);
        float2 dv0 = ds, dv1 = ds, dv2 = ds;
        for (int c0 = beg; c0 < end; c0 += CH) {
            int nc = min(CH, end - c0);
            __syncthreads();
            for (int i = tid; i < nc * 24; i += 128) {
                float v = egeo[(size_t)c0 * 24 + i];
                sG[i / 24][i % 24] = make_float2(v, v);
            }
            if (tid < nc) sS[tid] = esrc[c0 + tid];
            __syncthreads();
            for (int k = grp; k < nc; k += 2) {
                const float2* gk = sG[k];
                int src = sS[k];
                const float* pb = phi + (size_t)src * 384;
                float2 p0 = *(const float2*)(pb + f2);
                float2 p1, p2;
                p2 = *(const float2*)(pb + 256 + f2);
                float2 v0, v1, v2;
                if (!FIRST) {
                    p1 = *(const float2*)(pb + 128 + f2);
                    const float* vb = vin + (size_t)src * 384;
                    v0 = *(const float2*)(vb + f2);
                    v1 = *(const float2*)(vb + 128 + f2);
                    v2 = *(const float2*)(vb + 256 + f2);
                }
                float2 fc = gk[20];
                float2 wf1 = fmul2(fc, b1);
                float2 wf2 = FIRST ? make_float2(0.f, 0.f) : fmul2(fc, b2);
                float2 wf3 = fmul2(fc, b3);
#pragma unroll
                for (int r = 0; r < RR; r++) {
                    float2 rb = gk[r];
                    wf1 = ffma2(rb, w1[r], wf1);
                    if (!FIRST) wf2 = ffma2(rb, w2[r], wf2);
                    wf3 = ffma2(rb, w3[r], wf3);
                }
                ds = ffma2(p0, wf1, ds);
                float2 dvs = fmul2(p2, wf3);
                dv0 = ffma2(gk[21], dvs, dv0);
                dv1 = ffma2(gk[22], dvs, dv1);
                dv2 = ffma2(gk[23], dvs, dv2);
                if (!FIRST) {
                    float2 dvv = fmul2(p1, wf2);
                    dv0 = ffma2(v0, dvv, dv0);
                    dv1 = ffma2(v1, dvv, dv1);
                    dv2 = ffma2(v2, dvv, dv2);
                }
            }
        }
        // combine group partials
        if (grp == 1) {
            sP[t][0] = ds; sP[t][1] = dv0; sP[t][2] = dv1; sP[t][3] = dv2;
        }
        __syncthreads();
        if (grp == 0) {
            ds  = fadd2(ds,  sP[t][0]);
            dv0 = fadd2(dv0, sP[t][1]);
            dv1 = fadd2(dv1, sP[t][2]);
            dv2 = fadd2(dv2, sP[t][3]);

            size_t sa = (size_t)a * 128 + f2;
            size_t va = (size_t)a * 384 + f2;
            *(float2*)&s[sa] = fadd2(*(const float2*)&s[sa], ds);
            float2 o0, o1, o2;
            if (FIRST) {
                o0 = dv0; o1 = dv1; o2 = dv2;
            } else {
                o0 = fadd2(*(const float2*)&vin[va],       dv0);
                o1 = fadd2(*(const float2*)&vin[va + 128], dv1);
                o2 = fadd2(*(const float2*)&vin[va + 256], dv2);
            }
            *(float2*)&vout[va]       = o0;
            *(float2*)&vout[va + 128] = o1;
            *(float2*)&vout[va + 256] = o2;
            __nv_bfloat16 h0, h1, l0, l1;
            split_bf16(o0.x, h0, l0); split_bf16(o0.y, h1, l1);
            *(__nv_bfloat162*)&vbh[va]       = __nv_bfloat162(h0, h1);
            *(__nv_bfloat162*)&vbl[va]       = __nv_bfloat162(l0, l1);
            split_bf16(o1.x, h0, l0); split_bf16(o1.y, h1, l1);
            *(__nv_bfloat162*)&vbh[va + 128] = __nv_bfloat162(h0, h1);
            *(__nv_bfloat162*)&vbl[va + 128] = __nv_bfloat162(l0, l1);
            split_bf16(o2.x, h0, l0); split_bf16(o2.y, h1, l1);
            *(__nv_bfloat162*)&vbh[va + 256] = __nv_bfloat162(h0, h1);
            *(__nv_bfloat162*)&vbl[va + 256] = __nv_bfloat162(l0, l1);
        }
        __syncthreads();
    }
}

// ---------------- per-atom update pieces ------------------------------------
// uvv layout: [atom*3 + c][256] with cols 0..127 = uv, 128..255 = vv
__global__ void cat_kernel(const float* __restrict__ s, const float* __restrict__ uvv,
                           __nv_bfloat16* __restrict__ cth,
                           __nv_bfloat16* __restrict__ ctl) {
    int i = blockIdx.x * blockDim.x + threadIdx.x;
    if (i >= NA * FF) return;
    int atom = i >> 7, f = i & 127;
    size_t base = (size_t)atom * 3 * 256 + 128 + f;
    float x0 = uvv[base], x1 = uvv[base + 256], x2 = uvv[base + 512];
    float n = sqrtf(x0 * x0 + x1 * x1 + x2 * x2 + 1e-8f);
    __nv_bfloat16 h, l;
    size_t c0 = (size_t)atom * 256 + f;
    split_bf16(s[i], h, l);
    cth[c0] = h; ctl[c0] = l;
    split_bf16(n, h, l);
    cth[c0 + 128] = h; ctl[c0 + 128] = l;
}

__global__ void upd_kernel(const float* __restrict__ uvv,
                           const float* __restrict__ a,
                           float* __restrict__ s,
                           __nv_bfloat16* __restrict__ sh, __nv_bfloat16* __restrict__ sl,
                           const float* __restrict__ vB, float* __restrict__ vA) {
    int i = blockIdx.x * blockDim.x + threadIdx.x;
    if (i >= NA * FF) return;
    int atom = i >> 7, f = i & 127;
    size_t ub = (size_t)atom * 3 * 256 + f;
    float u0 = uvv[ub],       u1 = uvv[ub + 256], u2 = uvv[ub + 512];
    float x0 = uvv[ub + 128], x1 = uvv[ub + 384], x2 = uvv[ub + 640];
    float dot = u0 * x0 + u1 * x1 + u2 * x2;
    size_t off = (size_t)atom * 384;
    float a_vv = a[off + f], a_sv = a[off + 128 + f], a_ss = a[off + 256 + f];
    float sn = s[i] + a_ss + a_sv * dot;
    s[i] = sn;
    __nv_bfloat16 h, l;
    split_bf16(sn, h, l);
    sh[i] = h; sl[i] = l;
    vA[off + f]       = vB[off + f]       + a_vv * u0;
    vA[off + 128 + f] = vB[off + 128 + f] + a_vv * u1;
    vA[off + 256 + f] = vB[off + 256 + f] + a_vv * u2;
}

// ---------------- readout: GEMV + molecule segment sum ---------------------
__global__ void out2_kernel(const float* __restrict__ h, const float* __restrict__ w2,
                            const float* __restrict__ b2, const int* __restrict__ mol,
                            float* __restrict__ out) {
    int gw = (blockIdx.x * blockDim.x + threadIdx.x) >> 5;
    int lane = threadIdx.x & 31;
    if (gw >= NA) return;
    const float* hp = h + (size_t)gw * FF;
    float sum = 0.f;
#pragma unroll
    for (int i = lane; i < FF; i += 32) sum = fmaf(hp[i], w2[i], sum);
#pragma unroll
    for (int o = 16; o; o >>= 1) sum += __shfl_down_sync(0xffffffffu, sum, o);
    if (lane == 0) atomicAdd(&out[mol[gw]], sum + b2[0]);
}

// ---------------- host-side launch ------------------------------------------
static float* symf(const void* sym) {
    void* p = nullptr;
    cudaGetSymbolAddress(&p, sym);
    return (float*)p;
}
static int* symi(const void* sym) {
    void* p = nullptr;
    cudaGetSymbolAddress(&p, sym);
    return (int*)p;
}
static __nv_bfloat16* symb(const void* sym) {
    void* p = nullptr;
    cudaGetSymbolAddress(&p, sym);
    return (__nv_bfloat16*)p;
}

extern "C" void kernel_launch(void* const* d_in, const int* in_sizes, int n_in,
                              void* d_out, int out_size) {
    const int*   z        = (const int*)  d_in[0];
    const float* pos      = (const float*)d_in[1];
    const int*   edge_src = (const int*)  d_in[2];
    const int*   edge_dst = (const int*)  d_in[3];
    const int*   mol_idx  = (const int*)  d_in[4];
    const float* embed    = (const float*)d_in[5];
    const float* msg_w1   = (const float*)d_in[6];
    const float* msg_b1   = (const float*)d_in[7];
    const float* msg_w2   = (const float*)d_in[8];
    const float* msg_b2   = (const float*)d_in[9];
    const float* rbf_w    = (const float*)d_in[10];
    const float* rbf_b    = (const float*)d_in[11];
    const float* upd_u    = (const float*)d_in[12];
    const float* upd_v    = (const float*)d_in[13];
    const float* upd_a1   = (const float*)d_in[14];
    const float* upd_a1b  = (const float*)d_in[15];
    const float* upd_a2   = (const float*)d_in[16];
    const float* upd_a2b  = (const float*)d_in[17];
    const float* out_w1   = (const float*)d_in[18];
    const float* out_b1   = (const float*)d_in[19];
    const float* out_w2   = (const float*)d_in[20];
    const float* out_b2   = (const float*)d_in[21];
    float* out = (float*)d_out;

    float* s    = symf(g_s);
    float* vA   = symf(g_vA);
    float* vB   = symf(g_vB);
    float* h    = symf(g_h);
    float* phi  = symf(g_phi);
    float* uvv  = symf(g_uvv);
    float* a    = symf(g_a);
    float* egeo = symf(g_egeo);
    int* esrc   = symi(g_esrc);
    int* rowst  = symi(g_rowstart);
    int* cursor = symi(g_cursor);
    int* count  = symi(g_count);
    __nv_bfloat16* whi = symb(g_whi);
    __nv_bfloat16* wlo = symb(g_wlo);
    __nv_bfloat16* sh  = symb(g_sh),  *sl  = symb(g_sl);
    __nv_bfloat16* vbh = symb(g_vbh), *vbl = symb(g_vbl);
    __nv_bfloat16* cth = symb(g_cth), *ctl = symb(g_ctl);

    cudaFuncSetAttribute(gemm_mma<true,  false>, cudaFuncAttributeMaxDynamicSharedMemorySize, GT_SMEM);
    cudaFuncSetAttribute(gemm_mma<false, false>, cudaFuncAttributeMaxDynamicSharedMemorySize, GT_SMEM);
    cudaFuncSetAttribute(mlp2_kernel, cudaFuncAttributeMaxDynamicSharedMemorySize, MLP_SMEM);

    // prelude ordered so launch index 3 = first mlp2 (profiled slot)
    embed_kernel<<<(NA * 32 + 255) / 256, 256>>>(z, embed, s, sh, sl);
    wprep_all<<<(557056 + 255) / 256, 256>>>(msg_w1, msg_w2, upd_u, upd_v,
                                             upd_a1, upd_a2, out_w1, whi, wlo,
                                             count, out);
    count_kernel<<<(NE + 255) / 256, 256>>>(edge_dst, count);

    bool csr_done = false;
    for (int l = 0; l < LL; l++) {
        size_t LB = (size_t)l * 180224;
        const float* bb1 = msg_b1  + (size_t)l * FF;
        const float* bb2 = msg_b2  + (size_t)l * 3 * FF;
        const float* rw  = rbf_w   + (size_t)l * RR * 3 * FF;
        const float* rb  = rbf_b   + (size_t)l * 3 * FF;
        const float* a1b = upd_a1b + (size_t)l * FF;
        const float* a2b = upd_a2b + (size_t)l * 3 * FF;

        // fused s -> h -> phi
        mlp2_kernel<<<NA / 32, 256, MLP_SMEM>>>(sh, sl,
            whi + LB, wlo + LB, bb1,
            whi + LB + 16384, wlo + LB + 16384, bb2,
            phi, 128, 384);
        if (!csr_done) {
            scan_kernel<<<1, 1024>>>(count, rowst, cursor);
            fill_kernel<<<(NE + 255) / 256, 256>>>(edge_src, edge_dst, pos, cursor, egeo, esrc);
            csr_done = true;
        }
        if (l == 0)
            msg_kernel<true ><<<NA / APB, 128>>>(phi, vA, s, vB, vbh, vbl, rw, rb, egeo, esrc, rowst);
        else
            msg_kernel<false><<<NA / APB, 128>>>(phi, vA, s, vB, vbh, vbl, rw, rb, egeo, esrc, rowst);
        gemm_mma<false, false><<<dim3(4, 384), 128, GT_SMEM>>>(vbh, vbl,
            whi + LB + 65536, wlo + LB + 65536, nullptr, uvv, nullptr, nullptr, NA * 3, 256, 128);
        cat_kernel<<<(NA * FF + 255) / 256, 256>>>(s, uvv, cth, ctl);
        // fused cat -> ah -> a
        mlp2_kernel<<<NA / 32, 256, MLP_SMEM>>>(cth, ctl,
            whi + LB + 98304, wlo + LB + 98304, a1b,
            whi + LB + 131072, wlo + LB + 131072, a2b,
            a, 256, 384);
        upd_kernel<<<(NA * FF + 255) / 256, 256>>>(uvv, a, s, sh, sl, vB, vA);
    }

    gemm_mma<true, false><<<dim3(2, 128), 128, GT_SMEM>>>(sh, sl,
        whi + 540672, wlo + 540672, out_b1, h, nullptr, nullptr, NA, 128, 128);
    out2_kernel<<<NA * 32 / 256, 256>>>(h, out_w2, out_b2, mol_idx, out);
}

// round 11
// speedup vs baseline: 1.0321x; 1.0078x over previous
#include <cuda_runtime.h>
#include <cuda_bf16.h>
#include <cuda_fp16.h>
#include <math.h>
#include <stdint.h>

#define NA   8192
#define NE   262144
#define NMOL 128
#define FF   128
#define RR   20
#define LL   3
#define PI_F 3.14159265358979f

// ---------------- scratch (device globals; no runtime alloc allowed) -------
__device__ float g_s  [NA * FF];
__device__ float g_vA [NA * 3 * FF];
__device__ float g_vB [NA * 3 * FF];
__device__ float g_h  [NA * FF];
__device__ float g_uvv[NA * 3 * 2 * FF];      // fused [atom*3][256]: uv | vv
__device__ float g_a  [NA * 3 * FF];
__device__ float g_egeo[NE * 24];             // per sorted edge: rbf*fc[20], fc, unit[3]
__device__ int   g_esrc[NE];
__device__ int   g_rowstart[NA + 1];
__device__ int   g_cursor[NA];
__device__ int   g_count[NA];
// fp16 gather payloads for msg (phi and v), written by mlp2 / upd
__device__ __half g_ph16[NA * 3 * FF];
__device__ __half g_v16 [NA * 3 * FF];
// bf16 hi/lo weight blobs, N-major [n][k]
#define WBLOB_ELEMS (34 * 16384)
__device__ __nv_bfloat16 g_whi[WBLOB_ELEMS];
__device__ __nv_bfloat16 g_wlo[WBLOB_ELEMS];
// bf16 hi/lo activation (A-operand) arrays, k-major rows
__device__ __nv_bfloat16 g_sh [NA * FF],     g_sl [NA * FF];
__device__ __nv_bfloat16 g_vbh[NA * 3 * FF], g_vbl[NA * 3 * FF];
__device__ __nv_bfloat16 g_cth[NA * 2 * FF], g_ctl[NA * 2 * FF];

// ---------------- packed f32x2 helpers --------------------------------------
__device__ __forceinline__ float2 ffma2(float2 a, float2 b, float2 c) {
    float2 d;
    asm("fma.rn.f32x2 %0, %1, %2, %3;"
        : "=l"(*reinterpret_cast<unsigned long long*>(&d))
        : "l"(*reinterpret_cast<unsigned long long*>(&a)),
          "l"(*reinterpret_cast<unsigned long long*>(&b)),
          "l"(*reinterpret_cast<unsigned long long*>(&c)));
    return d;
}
__device__ __forceinline__ float2 fmul2(float2 a, float2 b) {
    float2 d;
    asm("mul.rn.f32x2 %0, %1, %2;"
        : "=l"(*reinterpret_cast<unsigned long long*>(&d))
        : "l"(*reinterpret_cast<unsigned long long*>(&a)),
          "l"(*reinterpret_cast<unsigned long long*>(&b)));
    return d;
}
__device__ __forceinline__ float2 fadd2(float2 a, float2 b) {
    float2 d;
    asm("add.rn.f32x2 %0, %1, %2;"
        : "=l"(*reinterpret_cast<unsigned long long*>(&d))
        : "l"(*reinterpret_cast<unsigned long long*>(&a)),
          "l"(*reinterpret_cast<unsigned long long*>(&b)));
    return d;
}
__device__ __forceinline__ void split_bf16(float x, __nv_bfloat16& h, __nv_bfloat16& l) {
    h = __float2bfloat16(x);
    l = __float2bfloat16(x - __bfloat162float(h));
}

// ---------------- init / small kernels --------------------------------------
__global__ void embed_kernel(const int* __restrict__ z,
                             const float* __restrict__ embed,
                             float* __restrict__ s,
                             __nv_bfloat16* __restrict__ sh,
                             __nv_bfloat16* __restrict__ sl) {
    int i = blockIdx.x * blockDim.x + threadIdx.x;
    if (i >= NA * 32) return;
    int atom = i >> 5, q = i & 31;
    float4 v = ((const float4*)(embed + (size_t)z[atom] * FF))[q];
    ((float4*)s)[i] = v;
    __nv_bfloat16 h0, h1, h2, h3, l0, l1, l2, l3;
    split_bf16(v.x, h0, l0); split_bf16(v.y, h1, l1);
    split_bf16(v.z, h2, l2); split_bf16(v.w, h3, l3);
    uint2 hp, lp;
    hp.x = ((uint32_t)__bfloat16_as_ushort(h1) << 16) | __bfloat16_as_ushort(h0);
    hp.y = ((uint32_t)__bfloat16_as_ushort(h3) << 16) | __bfloat16_as_ushort(h2);
    lp.x = ((uint32_t)__bfloat16_as_ushort(l1) << 16) | __bfloat16_as_ushort(l0);
    lp.y = ((uint32_t)__bfloat16_as_ushort(l3) << 16) | __bfloat16_as_ushort(l2);
    ((uint2*)sh)[i] = hp;
    ((uint2*)sl)[i] = lp;
}

// one-shot weight prep (+ init of count/out): fp32 W[K][N] -> bf16 hi/lo [n][K].
// Per-layer blob (elements): w1@0 w2@16384 u@65536 v@81920 a1@98304 a2@131072
// out_w1 @ 540672. Total 557056.
__global__ void wprep_all(const float* __restrict__ msg_w1,
                          const float* __restrict__ msg_w2,
                          const float* __restrict__ upd_u,
                          const float* __restrict__ upd_v,
                          const float* __restrict__ upd_a1,
                          const float* __restrict__ upd_a2,
                          const float* __restrict__ out_w1,
                          __nv_bfloat16* __restrict__ hi,
                          __nv_bfloat16* __restrict__ lo,
                          int* __restrict__ cnt, float* __restrict__ outp) {
    int i = blockIdx.x * blockDim.x + threadIdx.x;
    if (i < NA) cnt[i] = 0;
    if (i < NMOL) outp[i] = 0.f;
    if (i >= 557056) return;
    const float* src;
    int K, N, idx, segbase;
    if (i >= 540672) {
        src = out_w1; K = 128; N = 128; idx = i - 540672; segbase = 540672;
    } else {
        int l = i / 180224;
        int r = i - l * 180224;
        if (r < 16384)       { src = msg_w1 + l * 16384; K = 128; N = 128; idx = r;          segbase = l * 180224; }
        else if (r < 65536)  { src = msg_w2 + l * 49152; K = 128; N = 384; idx = r - 16384;  segbase = l * 180224 + 16384; }
        else if (r < 81920)  { src = upd_u  + l * 16384; K = 128; N = 128; idx = r - 65536;  segbase = l * 180224 + 65536; }
        else if (r < 98304)  { src = upd_v  + l * 16384; K = 128; N = 128; idx = r - 81920;  segbase = l * 180224 + 81920; }
        else if (r < 131072) { src = upd_a1 + l * 32768; K = 256; N = 128; idx = r - 98304;  segbase = l * 180224 + 98304; }
        else                 { src = upd_a2 + l * 49152; K = 128; N = 384; idx = r - 131072; segbase = l * 180224 + 131072; }
    }
    int k = idx / N, n = idx - k * N;
    float a = src[idx];
    __nv_bfloat16 h, l2;
    split_bf16(a, h, l2);
    hi[(size_t)segbase + (size_t)n * K + k] = h;
    lo[(size_t)segbase + (size_t)n * K + k] = l2;
}

// ---------------- CSR build + edge geometry --------------------------------
__global__ void count_kernel(const int* __restrict__ dst, int* __restrict__ cnt) {
    int e = blockIdx.x * blockDim.x + threadIdx.x;
    if (e < NE) atomicAdd(&cnt[dst[e]], 1);
}

__global__ void scan_kernel(const int* __restrict__ cnt,
                            int* __restrict__ rowstart,
                            int* __restrict__ cursor) {
    __shared__ int part[1024];
    int t = threadIdx.x;
    int loc[8], ex[8];
    int run = 0;
#pragma unroll
    for (int i = 0; i < 8; i++) {
        loc[i] = cnt[t * 8 + i];
        ex[i]  = run;
        run   += loc[i];
    }
    part[t] = run;
    __syncthreads();
    for (int off = 1; off < 1024; off <<= 1) {
        int v = (t >= off) ? part[t - off] : 0;
        __syncthreads();
        part[t] += v;
        __syncthreads();
    }
    int base = (t > 0) ? part[t - 1] : 0;
#pragma unroll
    for (int i = 0; i < 8; i++) {
        int rs = base + ex[i];
        rowstart[t * 8 + i] = rs;
        cursor[t * 8 + i]   = rs;
    }
    if (t == 1023) rowstart[NA] = part[1023];
}

__global__ void fill_kernel(const int* __restrict__ src,
                            const int* __restrict__ dst,
                            const float* __restrict__ pos,
                            int* __restrict__ cursor,
                            float* __restrict__ egeo,
                            int* __restrict__ esrc) {
    int e = blockIdx.x * blockDim.x + threadIdx.x;
    if (e >= NE) return;
    int sd = src[e], dd = dst[e];
    int p = atomicAdd(&cursor[dd], 1);
    float dx = pos[dd * 3 + 0] - pos[sd * 3 + 0];
    float dy = pos[dd * 3 + 1] - pos[sd * 3 + 1];
    float dz = pos[dd * 3 + 2] - pos[sd * 3 + 2];
    float d  = sqrtf(dx * dx + dy * dy + dz * dz + 1e-8f);
    float inv = 1.f / d;
    float fc = 0.5f * (cosf(PI_F * d / 5.0f) + 1.0f) * (d < 5.0f ? 1.f : 0.f);
    float* g = egeo + (size_t)p * 24;
#pragma unroll
    for (int r = 0; r < RR; r++) {
        float freq = (float)(r + 1) * (PI_F / 5.0f);
        g[r] = sinf(d * freq) * inv * fc;
    }
    g[20] = fc;
    g[21] = dx * inv; g[22] = dy * inv; g[23] = dz * inv;
    esrc[p] = sd;
}

// ---------------- MMA primitives --------------------------------------------
__device__ __forceinline__ void mma16816(float* d, const uint32_t* a, const uint32_t* b) {
    asm volatile(
        "mma.sync.aligned.m16n8k16.row.col.f32.bf16.bf16.f32 "
        "{%0,%1,%2,%3}, {%4,%5,%6,%7}, {%8,%9}, {%0,%1,%2,%3};"
        : "+f"(d[0]), "+f"(d[1]), "+f"(d[2]), "+f"(d[3])
        : "r"(a[0]), "r"(a[1]), "r"(a[2]), "r"(a[3]), "r"(b[0]), "r"(b[1]));
}
__device__ __forceinline__ void ldsm4(uint32_t* r, const __nv_bfloat16* p) {
    uint32_t addr = (uint32_t)__cvta_generic_to_shared(p);
    asm volatile("ldmatrix.sync.aligned.m8n8.x4.shared.b16 {%0,%1,%2,%3}, [%4];"
        : "=r"(r[0]), "=r"(r[1]), "=r"(r[2]), "=r"(r[3]) : "r"(addr));
}

// ---------------- standalone HMMA GEMM (64x64 CTA tile) ---------------------
#define GPAD 72
#define GT_SMEM (4 * 64 * GPAD * 2)

template <bool SILU, bool OSPLIT>
__global__ __launch_bounds__(128)
void gemm_mma(const __nv_bfloat16* __restrict__ Ahi_g,
              const __nv_bfloat16* __restrict__ Alo_g,
              const __nv_bfloat16* __restrict__ Whi,
              const __nv_bfloat16* __restrict__ Wlo,
              const float* __restrict__ bias, float* __restrict__ C,
              __nv_bfloat16* __restrict__ Chi, __nv_bfloat16* __restrict__ Clo,
              int M, int N, int K) {
    extern __shared__ __nv_bfloat16 sm[];
    __nv_bfloat16* Ahi = sm;
    __nv_bfloat16* Alo = sm + 64 * GPAD;
    __nv_bfloat16* Bhi = sm + 2 * 64 * GPAD;
    __nv_bfloat16* Blo = sm + 3 * 64 * GPAD;

    int tid = threadIdx.x, wid = tid >> 5, lane = tid & 31;
    int bm = blockIdx.y << 6, bn = blockIdx.x << 6;
    int wm = (wid & 1) << 5, wn = (wid >> 1) << 5;
    int g = lane >> 2, tg = lane & 3;

    float d[2][4][4];
#pragma unroll
    for (int mt = 0; mt < 2; mt++)
#pragma unroll
        for (int nt = 0; nt < 4; nt++)
#pragma unroll
            for (int q = 0; q < 4; q++) d[mt][nt][q] = 0.f;

    int a_row = (lane & 15), a_kh = (lane >> 4) << 3;
    int b_row = (lane & 7) + ((lane >> 4) << 3), b_kh = ((lane >> 3) & 1) << 3;

    for (int kc = 0; kc < K; kc += 64) {
#pragma unroll
        for (int it = 0; it < 4; it++) {
            int idx = it * 128 + tid;
            int r = idx >> 3, c = (idx & 7) << 3;
            *(uint4*)&Ahi[r * GPAD + c] = *(const uint4*)&Ahi_g[(size_t)(bm + r) * K + kc + c];
            *(uint4*)&Alo[r * GPAD + c] = *(const uint4*)&Alo_g[(size_t)(bm + r) * K + kc + c];
            *(uint4*)&Bhi[r * GPAD + c] = *(const uint4*)&Whi[(size_t)(bn + r) * K + kc + c];
            *(uint4*)&Blo[r * GPAD + c] = *(const uint4*)&Wlo[(size_t)(bn + r) * K + kc + c];
        }
        __syncthreads();

#pragma unroll
        for (int ks = 0; ks < 4; ks++) {
            int k0 = ks * 16;
            uint32_t ah[2][4], al[2][4], bh[2][4], bl[2][4];
#pragma unroll
            for (int mt = 0; mt < 2; mt++) {
                ldsm4(ah[mt], &Ahi[(wm + mt * 16 + a_row) * GPAD + k0 + a_kh]);
                ldsm4(al[mt], &Alo[(wm + mt * 16 + a_row) * GPAD + k0 + a_kh]);
            }
#pragma unroll
            for (int j = 0; j < 2; j++) {
                ldsm4(bh[j], &Bhi[(wn + j * 16 + b_row) * GPAD + k0 + b_kh]);
                ldsm4(bl[j], &Blo[(wn + j * 16 + b_row) * GPAD + k0 + b_kh]);
            }
#pragma unroll
            for (int mt = 0; mt < 2; mt++)
#pragma unroll
                for (int nt = 0; nt < 4; nt++) {
                    const uint32_t* bhp = &bh[nt >> 1][(nt & 1) << 1];
                    const uint32_t* blp = &bl[nt >> 1][(nt & 1) << 1];
                    mma16816(d[mt][nt], ah[mt], bhp);
                    mma16816(d[mt][nt], ah[mt], blp);
                    mma16816(d[mt][nt], al[mt], bhp);
                }
        }
        __syncthreads();
    }

#pragma unroll
    for (int mt = 0; mt < 2; mt++) {
        int row0 = bm + wm + mt * 16 + g;
#pragma unroll
        for (int nt = 0; nt < 4; nt++) {
            int col = bn + wn + nt * 8 + tg * 2;
            float b0 = 0.f, b1 = 0.f;
            if (bias) { b0 = bias[col]; b1 = bias[col + 1]; }
            float x0 = d[mt][nt][0] + b0, x1 = d[mt][nt][1] + b1;
            float x2 = d[mt][nt][2] + b0, x3 = d[mt][nt][3] + b1;
            if (SILU) {
                x0 = x0 / (1.f + __expf(-x0));
                x1 = x1 / (1.f + __expf(-x1));
                x2 = x2 / (1.f + __expf(-x2));
                x3 = x3 / (1.f + __expf(-x3));
            }
            if (OSPLIT) {
                __nv_bfloat16 h0, h1, h2, h3, l0, l1, l2, l3;
                split_bf16(x0, h0, l0); split_bf16(x1, h1, l1);
                split_bf16(x2, h2, l2); split_bf16(x3, h3, l3);
                *(__nv_bfloat162*)&Chi[(size_t)row0 * N + col]       = __nv_bfloat162(h0, h1);
                *(__nv_bfloat162*)&Clo[(size_t)row0 * N + col]       = __nv_bfloat162(l0, l1);
                *(__nv_bfloat162*)&Chi[(size_t)(row0 + 8) * N + col] = __nv_bfloat162(h2, h3);
                *(__nv_bfloat162*)&Clo[(size_t)(row0 + 8) * N + col] = __nv_bfloat162(l2, l3);
            } else {
                *(float2*)&C[(size_t)row0 * N + col]       = make_float2(x0, x1);
                *(float2*)&C[(size_t)(row0 + 8) * N + col] = make_float2(x2, x3);
            }
        }
    }
}

// ---------------- fused 2-layer MLP (32-row CTA, high occupancy) ------------
// C = (silu(A@W1+b1)) @ W2 + b2. A pre-split [m][K1]; W1 [128][K1]; W2 [N2][128].
// PHI16: write fp16 output (phi for msg gathers); else fp32.
#define XGP 136
#define MLP_SMEM (31744 * 2)

template <bool PHI16>
__global__ __launch_bounds__(256)
void mlp2_kernel(const __nv_bfloat16* __restrict__ Ahi_g,
                 const __nv_bfloat16* __restrict__ Alo_g,
                 const __nv_bfloat16* __restrict__ W1hi,
                 const __nv_bfloat16* __restrict__ W1lo,
                 const float* __restrict__ b1,
                 const __nv_bfloat16* __restrict__ W2hi,
                 const __nv_bfloat16* __restrict__ W2lo,
                 const float* __restrict__ b2,
                 float* __restrict__ C, __half* __restrict__ C16,
                 int K1, int N2) {
    extern __shared__ __nv_bfloat16 sm[];
    __nv_bfloat16* X1h = sm;
    __nv_bfloat16* X1l = sm + 4352;
    __nv_bfloat16* Ah  = sm + 8704;
    __nv_bfloat16* Al  = sm + 11008;
    __nv_bfloat16* Bh  = sm + 13312;
    __nv_bfloat16* Bl  = sm + 22528;

    int tid = threadIdx.x, wid = tid >> 5, lane = tid & 31;
    int bm = blockIdx.x << 5;        // 32 rows
    int wm = (wid & 1) << 4;         // 2 m-warps of 16
    int wn = (wid >> 1) << 5;        // 4 n-warps over 128
    int g = lane >> 2, tg = lane & 3;
    int a_row = (lane & 15), a_kh = (lane >> 4) << 3;
    int b_row = (lane & 7) + ((lane >> 4) << 3), b_kh = ((lane >> 3) & 1) << 3;

    // ---------------- stage 1: X1 = silu(A @ W1 + b1), 32 x 128 -------------
    float d[4][4];
#pragma unroll
    for (int nt = 0; nt < 4; nt++)
#pragma unroll
        for (int q = 0; q < 4; q++) d[nt][q] = 0.f;

    for (int kc = 0; kc < K1; kc += 64) {
        {
            int r = tid >> 3, c = (tid & 7) << 3;
            *(uint4*)&Ah[r * GPAD + c] = *(const uint4*)&Ahi_g[(size_t)(bm + r) * K1 + kc + c];
            *(uint4*)&Al[r * GPAD + c] = *(const uint4*)&Alo_g[(size_t)(bm + r) * K1 + kc + c];
        }
#pragma unroll
        for (int it = 0; it < 4; it++) {
            int idx = it * 256 + tid;
            int r = idx >> 3, c = (idx & 7) << 3;
            *(uint4*)&Bh[r * GPAD + c] = *(const uint4*)&W1hi[(size_t)r * K1 + kc + c];
            *(uint4*)&Bl[r * GPAD + c] = *(const uint4*)&W1lo[(size_t)r * K1 + kc + c];
        }
        __syncthreads();
#pragma unroll
        for (int ks = 0; ks < 4; ks++) {
            int k0 = ks * 16;
            uint32_t ah[4], al[4], bh[2][4], bl[2][4];
            ldsm4(ah, &Ah[(wm + a_row) * GPAD + k0 + a_kh]);
            ldsm4(al, &Al[(wm + a_row) * GPAD + k0 + a_kh]);
#pragma unroll
            for (int j = 0; j < 2; j++) {
                ldsm4(bh[j], &Bh[(wn + j * 16 + b_row) * GPAD + k0 + b_kh]);
                ldsm4(bl[j], &Bl[(wn + j * 16 + b_row) * GPAD + k0 + b_kh]);
            }
#pragma unroll
            for (int nt = 0; nt < 4; nt++) {
                const uint32_t* bhp = &bh[nt >> 1][(nt & 1) << 1];
                const uint32_t* blp = &bl[nt >> 1][(nt & 1) << 1];
                mma16816(d[nt], ah, bhp);
                mma16816(d[nt], ah, blp);
                mma16816(d[nt], al, bhp);
            }
        }
        __syncthreads();
    }

    // bias + silu + split -> X1 smem (bf16 hi/lo)
    {
        int r0 = wm + g;
#pragma unroll
        for (int nt = 0; nt < 4; nt++) {
            int col = wn + nt * 8 + tg * 2;
            float b0 = b1[col], bb = b1[col + 1];
            float x0 = d[nt][0] + b0, x1 = d[nt][1] + bb;
            float x2 = d[nt][2] + b0, x3 = d[nt][3] + bb;
            x0 = x0 / (1.f + __expf(-x0));
            x1 = x1 / (1.f + __expf(-x1));
            x2 = x2 / (1.f + __expf(-x2));
            x3 = x3 / (1.f + __expf(-x3));
            __nv_bfloat16 h0, h1, h2, h3, l0, l1, l2, l3;
            split_bf16(x0, h0, l0); split_bf16(x1, h1, l1);
            split_bf16(x2, h2, l2); split_bf16(x3, h3, l3);
            *(__nv_bfloat162*)&X1h[r0 * XGP + col]       = __nv_bfloat162(h0, h1);
            *(__nv_bfloat162*)&X1l[r0 * XGP + col]       = __nv_bfloat162(l0, l1);
            *(__nv_bfloat162*)&X1h[(r0 + 8) * XGP + col] = __nv_bfloat162(h2, h3);
            *(__nv_bfloat162*)&X1l[(r0 + 8) * XGP + col] = __nv_bfloat162(l2, l3);
        }
    }
    __syncthreads();

    // ---------------- stage 2: C = X1 @ W2 + b2, 32 x N2 --------------------
    for (int nc = 0; nc < N2; nc += 128) {
        float e[4][4];
#pragma unroll
        for (int nt = 0; nt < 4; nt++)
#pragma unroll
            for (int q = 0; q < 4; q++) e[nt][q] = 0.f;

        for (int kc2 = 0; kc2 < 2; kc2++) {
            __syncthreads();
#pragma unroll
            for (int it = 0; it < 4; it++) {
                int idx = it * 256 + tid;
                int r = idx >> 3, c = (idx & 7) << 3;
                *(uint4*)&Bh[r * GPAD + c] = *(const uint4*)&W2hi[(size_t)(nc + r) * 128 + kc2 * 64 + c];
                *(uint4*)&Bl[r * GPAD + c] = *(const uint4*)&W2lo[(size_t)(nc + r) * 128 + kc2 * 64 + c];
            }
            __syncthreads();
#pragma unroll
            for (int ks = 0; ks < 4; ks++) {
                int k0 = ks * 16;
                int ka = kc2 * 64 + k0;
                uint32_t ah[4], al[4], bh[2][4], bl[2][4];
                ldsm4(ah, &X1h[(wm + a_row) * XGP + ka + a_kh]);
                ldsm4(al, &X1l[(wm + a_row) * XGP + ka + a_kh]);
#pragma unroll
                for (int j = 0; j < 2; j++) {
                    ldsm4(bh[j], &Bh[(wn + j * 16 + b_row) * GPAD + k0 + b_kh]);
                    ldsm4(bl[j], &Bl[(wn + j * 16 + b_row) * GPAD + k0 + b_kh]);
                }
#pragma unroll
                for (int nt = 0; nt < 4; nt++) {
                    const uint32_t* bhp = &bh[nt >> 1][(nt & 1) << 1];
                    const uint32_t* blp = &bl[nt >> 1][(nt & 1) << 1];
                    mma16816(e[nt], ah, bhp);
                    mma16816(e[nt], ah, blp);
                    mma16816(e[nt], al, bhp);
                }
            }
        }
        {
            int row0 = bm + wm + g;
#pragma unroll
            for (int nt = 0; nt < 4; nt++) {
                int col = nc + wn + nt * 8 + tg * 2;
                float b0 = b2[col], bb = b2[col + 1];
                float x0 = e[nt][0] + b0, x1 = e[nt][1] + bb;
                float x2 = e[nt][2] + b0, x3 = e[nt][3] + bb;
                if (PHI16) {
                    *(__half2*)&C16[(size_t)row0 * N2 + col]       = __floats2half2_rn(x0, x1);
                    *(__half2*)&C16[(size_t)(row0 + 8) * N2 + col] = __floats2half2_rn(x2, x3);
                } else {
                    *(float2*)&C[(size_t)row0 * N2 + col]       = make_float2(x0, x1);
                    *(float2*)&C[(size_t)(row0 + 8) * N2 + col] = make_float2(x2, x3);
                }
            }
        }
    }
}

// ---------------- message pass (CSR gather, fp16 payloads) ------------------
#define APB 4
#define CH  32
__device__ __forceinline__ float2 h2f2(const __half* p) {
    return __half22float2(*(const __half2*)p);
}
template <bool FIRST>
__global__ __launch_bounds__(128)
void msg_kernel(const __half* __restrict__ phi16, const float* __restrict__ vin,
                const __half* __restrict__ v16,
                float* __restrict__ s, float* __restrict__ vout,
                __nv_bfloat16* __restrict__ vbh, __nv_bfloat16* __restrict__ vbl,
                const float* __restrict__ rbfW, const float* __restrict__ rbfB,
                const float* __restrict__ egeo, const int* __restrict__ esrc,
                const int* __restrict__ rowstart) {
    int tid = threadIdx.x;
    int t   = tid & 63;                  // feature pair (2t, 2t+1)
    int grp = tid >> 6;                  // edge group 0/1
    int f2 = t * 2;
    float2 w1[RR], w2[RR], w3[RR];
#pragma unroll
    for (int r = 0; r < RR; r++) {
        w1[r] = *(const float2*)&rbfW[r * 384 + f2];
        if (!FIRST) w2[r] = *(const float2*)&rbfW[r * 384 + 128 + f2];
        w3[r] = *(const float2*)&rbfW[r * 384 + 256 + f2];
    }
    float2 b1 = *(const float2*)&rbfB[f2];
    float2 b2 = FIRST ? make_float2(0.f, 0.f) : *(const float2*)&rbfB[128 + f2];
    float2 b3 = *(const float2*)&rbfB[256 + f2];

    __shared__ float2 sG[CH][24];        // per-edge scalars duplicated {v,v}
    __shared__ int    sS[CH];
    __shared__ float2 sP[64][4];         // group-1 partials: ds,dv0,dv1,dv2

    int a0 = blockIdx.x * APB;
    for (int a = a0; a < a0 + APB; a++) {
        int beg = rowstart[a], end = rowstart[a + 1];
        float2 ds  = make_float2(0.f, 0.f);
        float2 dv0 = ds, dv1 = ds, dv2 = ds;
        for (int c0 = beg; c0 < end; c0 += CH) {
            int nc = min(CH, end - c0);
            __syncthreads();
            for (int i = tid; i < nc * 24; i += 128) {
                float v = egeo[(size_t)c0 * 24 + i];
                sG[i / 24][i % 24] = make_float2(v, v);
            }
            if (tid < nc) sS[tid] = esrc[c0 + tid];
            __syncthreads();
            for (int k = grp; k < nc; k += 2) {
                const float2* gk = sG[k];
                int src = sS[k];
                const __half* pb = phi16 + (size_t)src * 384;
                float2 p0 = h2f2(pb + f2);
                float2 p1, p2;
                p2 = h2f2(pb + 256 + f2);
                float2 v0, v1, v2;
                if (!FIRST) {
                    p1 = h2f2(pb + 128 + f2);
                    const __half* vb = v16 + (size_t)src * 384;
                    v0 = h2f2(vb + f2);
                    v1 = h2f2(vb + 128 + f2);
                    v2 = h2f2(vb + 256 + f2);
                }
                float2 fc = gk[20];
                float2 wf1 = fmul2(fc, b1);
                float2 wf2 = FIRST ? make_float2(0.f, 0.f) : fmul2(fc, b2);
                float2 wf3 = fmul2(fc, b3);
#pragma unroll
                for (int r = 0; r < RR; r++) {
                    float2 rb = gk[r];
                    wf1 = ffma2(rb, w1[r], wf1);
                    if (!FIRST) wf2 = ffma2(rb, w2[r], wf2);
                    wf3 = ffma2(rb, w3[r], wf3);
                }
                ds = ffma2(p0, wf1, ds);
                float2 dvs = fmul2(p2, wf3);
                dv0 = ffma2(gk[21], dvs, dv0);
                dv1 = ffma2(gk[22], dvs, dv1);
                dv2 = ffma2(gk[23], dvs, dv2);
                if (!FIRST) {
                    float2 dvv = fmul2(p1, wf2);
                    dv0 = ffma2(v0, dvv, dv0);
                    dv1 = ffma2(v1, dvv, dv1);
                    dv2 = ffma2(v2, dvv, dv2);
                }
            }
        }
        // combine group partials
        if (grp == 1) {
            sP[t][0] = ds; sP[t][1] = dv0; sP[t][2] = dv1; sP[t][3] = dv2;
        }
        __syncthreads();
        if (grp == 0) {
            ds  = fadd2(ds,  sP[t][0]);
            dv0 = fadd2(dv0, sP[t][1]);
            dv1 = fadd2(dv1, sP[t][2]);
            dv2 = fadd2(dv2, sP[t][3]);

            size_t sa = (size_t)a * 128 + f2;
            size_t va = (size_t)a * 384 + f2;
            *(float2*)&s[sa] = fadd2(*(const float2*)&s[sa], ds);
            float2 o0, o1, o2;
            if (FIRST) {
                o0 = dv0; o1 = dv1; o2 = dv2;
            } else {
                o0 = fadd2(*(const float2*)&vin[va],       dv0);
                o1 = fadd2(*(const float2*)&vin[va + 128], dv1);
                o2 = fadd2(*(const float2*)&vin[va + 256], dv2);
            }
            *(float2*)&vout[va]       = o0;
            *(float2*)&vout[va + 128] = o1;
            *(float2*)&vout[va + 256] = o2;
            __nv_bfloat16 h0, h1, l0, l1;
            split_bf16(o0.x, h0, l0); split_bf16(o0.y, h1, l1);
            *(__nv_bfloat162*)&vbh[va]       = __nv_bfloat162(h0, h1);
            *(__nv_bfloat162*)&vbl[va]       = __nv_bfloat162(l0, l1);
            split_bf16(o1.x, h0, l0); split_bf16(o1.y, h1, l1);
            *(__nv_bfloat162*)&vbh[va + 128] = __nv_bfloat162(h0, h1);
            *(__nv_bfloat162*)&vbl[va + 128] = __nv_bfloat162(l0, l1);
            split_bf16(o2.x, h0, l0); split_bf16(o2.y, h1, l1);
            *(__nv_bfloat162*)&vbh[va + 256] = __nv_bfloat162(h0, h1);
            *(__nv_bfloat162*)&vbl[va + 256] = __nv_bfloat162(l0, l1);
        }
        __syncthreads();
    }
}

// ---------------- per-atom update pieces ------------------------------------
// uvv layout: [atom*3 + c][256] with cols 0..127 = uv, 128..255 = vv
__global__ void cat_kernel(const float* __restrict__ s, const float* __restrict__ uvv,
                           __nv_bfloat16* __restrict__ cth,
                           __nv_bfloat16* __restrict__ ctl) {
    int i = blockIdx.x * blockDim.x + threadIdx.x;
    if (i >= NA * FF) return;
    int atom = i >> 7, f = i & 127;
    size_t base = (size_t)atom * 3 * 256 + 128 + f;
    float x0 = uvv[base], x1 = uvv[base + 256], x2 = uvv[base + 512];
    float n = sqrtf(x0 * x0 + x1 * x1 + x2 * x2 + 1e-8f);
    __nv_bfloat16 h, l;
    size_t c0 = (size_t)atom * 256 + f;
    split_bf16(s[i], h, l);
    cth[c0] = h; ctl[c0] = l;
    split_bf16(n, h, l);
    cth[c0 + 128] = h; ctl[c0 + 128] = l;
}

__global__ void upd_kernel(const float* __restrict__ uvv,
                           const float* __restrict__ a,
                           float* __restrict__ s,
                           __nv_bfloat16* __restrict__ sh, __nv_bfloat16* __restrict__ sl,
                           const float* __restrict__ vB, float* __restrict__ vA,
                           __half* __restrict__ v16) {
    int i = blockIdx.x * blockDim.x + threadIdx.x;
    if (i >= NA * FF) return;
    int atom = i >> 7, f = i & 127;
    size_t ub = (size_t)atom * 3 * 256 + f;
    float u0 = uvv[ub],       u1 = uvv[ub + 256], u2 = uvv[ub + 512];
    float x0 = uvv[ub + 128], x1 = uvv[ub + 384], x2 = uvv[ub + 640];
    float dot = u0 * x0 + u1 * x1 + u2 * x2;
    size_t off = (size_t)atom * 384;
    float a_vv = a[off + f], a_sv = a[off + 128 + f], a_ss = a[off + 256 + f];
    float sn = s[i] + a_ss + a_sv * dot;
    s[i] = sn;
    __nv_bfloat16 h, l;
    split_bf16(sn, h, l);
    sh[i] = h; sl[i] = l;
    float n0 = vB[off + f]       + a_vv * u0;
    float n1 = vB[off + 128 + f] + a_vv * u1;
    float n2 = vB[off + 256 + f] + a_vv * u2;
    vA[off + f]       = n0;
    vA[off + 128 + f] = n1;
    vA[off + 256 + f] = n2;
    v16[off + f]       = __float2half(n0);
    v16[off + 128 + f] = __float2half(n1);
    v16[off + 256 + f] = __float2half(n2);
}

// ---------------- readout: GEMV + molecule segment sum ---------------------
__global__ void out2_kernel(const float* __restrict__ h, const float* __restrict__ w2,
                            const float* __restrict__ b2, const int* __restrict__ mol,
                            float* __restrict__ out) {
    int gw = (blockIdx.x * blockDim.x + threadIdx.x) >> 5;
    int lane = threadIdx.x & 31;
    if (gw >= NA) return;
    const float* hp = h + (size_t)gw * FF;
    float sum = 0.f;
#pragma unroll
    for (int i = lane; i < FF; i += 32) sum = fmaf(hp[i], w2[i], sum);
#pragma unroll
    for (int o = 16; o; o >>= 1) sum += __shfl_down_sync(0xffffffffu, sum, o);
    if (lane == 0) atomicAdd(&out[mol[gw]], sum + b2[0]);
}

// ---------------- host-side launch ------------------------------------------
static float* symf(const void* sym) {
    void* p = nullptr;
    cudaGetSymbolAddress(&p, sym);
    return (float*)p;
}
static int* symi(const void* sym) {
    void* p = nullptr;
    cudaGetSymbolAddress(&p, sym);
    return (int*)p;
}
static __nv_bfloat16* symb(const void* sym) {
    void* p = nullptr;
    cudaGetSymbolAddress(&p, sym);
    return (__nv_bfloat16*)p;
}
static __half* symh(const void* sym) {
    void* p = nullptr;
    cudaGetSymbolAddress(&p, sym);
    return (__half*)p;
}

extern "C" void kernel_launch(void* const* d_in, const int* in_sizes, int n_in,
                              void* d_out, int out_size) {
    const int*   z        = (const int*)  d_in[0];
    const float* pos      = (const float*)d_in[1];
    const int*   edge_src = (const int*)  d_in[2];
    const int*   edge_dst = (const int*)  d_in[3];
    const int*   mol_idx  = (const int*)  d_in[4];
    const float* embed    = (const float*)d_in[5];
    const float* msg_w1   = (const float*)d_in[6];
    const float* msg_b1   = (const float*)d_in[7];
    const float* msg_w2   = (const float*)d_in[8];
    const float* msg_b2   = (const float*)d_in[9];
    const float* rbf_w    = (const float*)d_in[10];
    const float* rbf_b    = (const float*)d_in[11];
    const float* upd_u    = (const float*)d_in[12];
    const float* upd_v    = (const float*)d_in[13];
    const float* upd_a1   = (const float*)d_in[14];
    const float* upd_a1b  = (const float*)d_in[15];
    const float* upd_a2   = (const float*)d_in[16];
    const float* upd_a2b  = (const float*)d_in[17];
    const float* out_w1   = (const float*)d_in[18];
    const float* out_b1   = (const float*)d_in[19];
    const float* out_w2   = (const float*)d_in[20];
    const float* out_b2   = (const float*)d_in[21];
    float* out = (float*)d_out;

    float* s    = symf(g_s);
    float* vA   = symf(g_vA);
    float* vB   = symf(g_vB);
    float* h    = symf(g_h);
    float* uvv  = symf(g_uvv);
    float* a    = symf(g_a);
    float* egeo = symf(g_egeo);
    int* esrc   = symi(g_esrc);
    int* rowst  = symi(g_rowstart);
    int* cursor = symi(g_cursor);
    int* count  = symi(g_count);
    __nv_bfloat16* whi = symb(g_whi);
    __nv_bfloat16* wlo = symb(g_wlo);
    __nv_bfloat16* sh  = symb(g_sh),  *sl  = symb(g_sl);
    __nv_bfloat16* vbh = symb(g_vbh), *vbl = symb(g_vbl);
    __nv_bfloat16* cth = symb(g_cth), *ctl = symb(g_ctl);
    __half* ph16 = symh(g_ph16);
    __half* v16  = symh(g_v16);

    cudaFuncSetAttribute(gemm_mma<true,  false>, cudaFuncAttributeMaxDynamicSharedMemorySize, GT_SMEM);
    cudaFuncSetAttribute(gemm_mma<false, false>, cudaFuncAttributeMaxDynamicSharedMemorySize, GT_SMEM);
    cudaFuncSetAttribute(mlp2_kernel<true >, cudaFuncAttributeMaxDynamicSharedMemorySize, MLP_SMEM);
    cudaFuncSetAttribute(mlp2_kernel<false>, cudaFuncAttributeMaxDynamicSharedMemorySize, MLP_SMEM);

    // prelude ordered so launch index 3 = first mlp2 (profiled slot)
    embed_kernel<<<(NA * 32 + 255) / 256, 256>>>(z, embed, s, sh, sl);
    wprep_all<<<(557056 + 255) / 256, 256>>>(msg_w1, msg_w2, upd_u, upd_v,
                                             upd_a1, upd_a2, out_w1, whi, wlo,
                                             count, out);
    count_kernel<<<(NE + 255) / 256, 256>>>(edge_dst, count);

    bool csr_done = false;
    for (int l = 0; l < LL; l++) {
        size_t LB = (size_t)l * 180224;
        const float* bb1 = msg_b1  + (size_t)l * FF;
        const float* bb2 = msg_b2  + (size_t)l * 3 * FF;
        const float* rw  = rbf_w   + (size_t)l * RR * 3 * FF;
        const float* rb  = rbf_b   + (size_t)l * 3 * FF;
        const float* a1b = upd_a1b + (size_t)l * FF;
        const float* a2b = upd_a2b + (size_t)l * 3 * FF;

        // fused s -> h -> phi (fp16 output for gathers)
        mlp2_kernel<true><<<NA / 32, 256, MLP_SMEM>>>(sh, sl,
            whi + LB, wlo + LB, bb1,
            whi + LB + 16384, wlo + LB + 16384, bb2,
            nullptr, ph16, 128, 384);
        if (!csr_done) {
            scan_kernel<<<1, 1024>>>(count, rowst, cursor);
            fill_kernel<<<(NE + 255) / 256, 256>>>(edge_src, edge_dst, pos, cursor, egeo, esrc);
            csr_done = true;
        }
        if (l == 0)
            msg_kernel<true ><<<NA / APB, 128>>>(ph16, vA, v16, s, vB, vbh, vbl, rw, rb, egeo, esrc, rowst);
        else
            msg_kernel<false><<<NA / APB, 128>>>(ph16, vA, v16, s, vB, vbh, vbl, rw, rb, egeo, esrc, rowst);
        gemm_mma<false, false><<<dim3(4, 384), 128, GT_SMEM>>>(vbh, vbl,
            whi + LB + 65536, wlo + LB + 65536, nullptr, uvv, nullptr, nullptr, NA * 3, 256, 128);
        cat_kernel<<<(NA * FF + 255) / 256, 256>>>(s, uvv, cth, ctl);
        // fused cat -> ah -> a (fp32 output)
        mlp2_kernel<false><<<NA / 32, 256, MLP_SMEM>>>(cth, ctl,
            whi + LB + 98304, wlo + LB + 98304, a1b,
            whi + LB + 131072, wlo + LB + 131072, a2b,
            a, nullptr, 256, 384);
        upd_kernel<<<(NA * FF + 255) / 256, 256>>>(uvv, a, s, sh, sl, vB, vA, v16);
    }

    gemm_mma<true, false><<<dim3(2, 128), 128, GT_SMEM>>>(sh, sl,
        whi + 540672, wlo + 540672, out_b1, h, nullptr, nullptr, NA, 128, 128);
    out2_kernel<<<NA * 32 / 256, 256>>>(h, out_w2, out_b2, mol_idx, out);
}